// round 9
// baseline (speedup 1.0000x reference)
#include <cuda_runtime.h>
#include <math.h>

#define BB 32
#define SS 512
#define II 512
#define HH 1024
#define G3 3072
#define H2 2048

#define W_SM_FLOATS (1024 * 48)         // per-CTA W slice: 196,608 B
#define HSTAGE_FLOATS (8 * 2 * 512)     // 8 groups x 2 bufs x (16k x 32b) = 32 KB
#define GRU_SMEM_BYTES ((W_SM_FLOATS + HSTAGE_FLOATS) * 4)   // 229,376 B

// ---------------- device scratch ----------------
__device__ float g_wih0_t[2][II * G3];
__device__ float g_wih1_t[2][(size_t)H2 * G3];
__device__ float g_whh_p[2][2][HH * G3];
__device__ float g_gx[2][(size_t)BB * SS * G3];
__device__ float g_h[2][2][HH * BB];            // [dir][parity][j][b]
__device__ float g_out0[(size_t)BB * SS * H2];
__device__ unsigned g_bar_flags[2][64];         // per-CTA arrival step counters

// ---------------- helpers ----------------
__device__ __forceinline__ float2 ffma2(float2 a, float2 b, float2 c) {
    unsigned long long A = *reinterpret_cast<unsigned long long*>(&a);
    unsigned long long B = *reinterpret_cast<unsigned long long*>(&b);
    unsigned long long C = *reinterpret_cast<unsigned long long*>(&c);
    unsigned long long D;
    asm("fma.rn.f32x2 %0, %1, %2, %3;" : "=l"(D) : "l"(A), "l"(B), "l"(C));
    return *reinterpret_cast<float2*>(&D);
}
__device__ __forceinline__ float2 bcast2(float x) { return make_float2(x, x); }
__device__ __forceinline__ float sigmoidf_(float x) { return 1.0f / (1.0f + expf(-x)); }

__device__ __forceinline__ float4 ldcg4(const float* p) {
    float4 v;
    asm volatile("ld.global.cg.v4.f32 {%0,%1,%2,%3}, [%4];"
                 : "=f"(v.x), "=f"(v.y), "=f"(v.z), "=f"(v.w) : "l"(p));
    return v;
}
__device__ __forceinline__ float2 ldcg2(const float* p) {
    float2 v;
    asm volatile("ld.global.cg.v2.f32 {%0,%1}, [%2];" : "=f"(v.x), "=f"(v.y) : "l"(p));
    return v;
}
__device__ __forceinline__ void cpasync16(unsigned dst, const float* src) {
    asm volatile("cp.async.cg.shared.global [%0], [%1], 16;" :: "r"(dst), "l"(src) : "memory");
}
#define GROUP_BAR(id) asm volatile("bar.sync %0, 64;" :: "r"(id) : "memory")

// flag-array grid barrier per direction: no atomic contention.
// Arrival: one st.release per CTA to its own slot. Wait: warp 0 polls all 64
// flags in parallel (2 acquire-loads per lane + ballot), others wait at bar 0.
__device__ __forceinline__ void dir_barrier(int dir, unsigned n) {
    __syncthreads();
    unsigned* flags = g_bar_flags[dir];
    if (threadIdx.x == 0) {
        asm volatile("st.release.gpu.global.u32 [%0], %1;"
                     :: "l"(flags + blockIdx.x), "r"(n) : "memory");
    }
    if (threadIdx.x < 32) {
        const unsigned lane = threadIdx.x;
        for (;;) {
            unsigned v0, v1;
            asm volatile("ld.acquire.gpu.global.u32 %0, [%1];"
                         : "=r"(v0) : "l"(flags + lane) : "memory");
            asm volatile("ld.acquire.gpu.global.u32 %0, [%1];"
                         : "=r"(v1) : "l"(flags + 32 + lane) : "memory");
            if (__all_sync(0xffffffffu, (v0 >= n) && (v1 >= n))) break;
            __nanosleep(32);
        }
    }
    __syncthreads();
}

// ---------------- batched transpose for w_ih: in[3072][K] -> out[K][3072] ----------------
__global__ void transpose_ih(const float* f0, const float* b0,
                             const float* f1, const float* b1,
                             float* df0, float* db0, float* df1, float* db1) {
    __shared__ float tile[32][33];
    const float* in; float* out; int K;
    switch (blockIdx.z) {
        case 0: in = f0; out = df0; K = II; break;
        case 1: in = b0; out = db0; K = II; break;
        case 2: in = f1; out = df1; K = H2; break;
        default: in = b1; out = db1; K = H2; break;
    }
    int n0 = blockIdx.x * 32, k0 = blockIdx.y * 32;
    if (k0 >= K) return;
    for (int i = threadIdx.y; i < 32; i += 8)
        tile[i][threadIdx.x] = in[(size_t)(n0 + i) * K + k0 + threadIdx.x];
    __syncthreads();
    for (int i = threadIdx.y; i < 32; i += 8)
        out[(size_t)(k0 + i) * G3 + n0 + threadIdx.x] = tile[threadIdx.x][i];
}

// ---------------- prepack W_hh into [jblk][k][g][jp][c] + zero h / barriers ----------------
__global__ void prepack_whh(const float* w00, const float* w01,
                            const float* w10, const float* w11) {
    int mat = blockIdx.y;
    const float* src = (mat == 0) ? w00 : (mat == 1) ? w01 : (mat == 2) ? w10 : w11;
    float* dst = g_whh_p[mat >> 1][mat & 1];
    int idx = blockIdx.x * 256 + threadIdx.x;   // n*1024 + k
    int k = idx & 1023;
    int n = idx >> 10;
    int g = n >> 10;
    int nj = n & 1023;
    int jblk = nj >> 4;
    int jp = (nj >> 1) & 7;
    int c  = nj & 1;
    dst[jblk * W_SM_FLOATS + k * 48 + g * 16 + jp * 2 + c] = src[idx];
    if (mat == 0) {
        if (idx < HH * BB) { g_h[0][0][idx] = 0.f; g_h[1][0][idx] = 0.f; }
        if (idx < 128) g_bar_flags[idx >> 6][idx & 63] = 0u;
    }
}

// ---------------- SGEMM 128x128x16, double-buffered, conflict-light B reads ----------------
__global__ __launch_bounds__(256, 2) void gemm_gx2(
    const float* __restrict__ X, int strideB, int strideS, int K,
    const float* __restrict__ Wt0, const float* __restrict__ Wt1,
    const float* __restrict__ bias0, const float* __restrict__ bias1,
    float* __restrict__ C0, float* __restrict__ C1)
{
    __shared__ float As[2][16][128];
    __shared__ float Bs[2][16][128];
    const float* Wt   = blockIdx.z ? Wt1 : Wt0;
    const float* bias = blockIdx.z ? bias1 : bias0;
    float* C          = blockIdx.z ? C1 : C0;

    const int tid = threadIdx.x;
    const int bn = blockIdx.x * 128;
    const int bm = blockIdx.y * 128;
    const int tx = tid & 15, ty = tid >> 4;

    const int rowA0 = tid >> 2;
    const int rowA1 = rowA0 + 64;
    const int qa = tid & 3;
    int m0 = bm + rowA0, m1 = bm + rowA1;
    const float* Xr0 = X + (size_t)(m0 & 31) * strideB + (size_t)(m0 >> 5) * strideS + qa * 4;
    const float* Xr1 = X + (size_t)(m1 & 31) * strideB + (size_t)(m1 >> 5) * strideS + qa * 4;
    const int krB = tid >> 5;
    const int nqB = tid & 31;
    const float* Wp0 = Wt + (size_t)krB * G3 + bn + nqB * 4;
    const float* Wp1 = Wt + (size_t)(krB + 8) * G3 + bn + nqB * 4;

    float2 acc[8][4];
#pragma unroll
    for (int i = 0; i < 8; i++)
#pragma unroll
        for (int j = 0; j < 4; j++) acc[i][j] = make_float2(0.f, 0.f);

    float4 ra0 = *(const float4*)(Xr0);
    float4 ra1 = *(const float4*)(Xr1);
    float4 rb0 = *(const float4*)(Wp0);
    float4 rb1 = *(const float4*)(Wp1);
    As[0][qa * 4 + 0][rowA0] = ra0.x;
    As[0][qa * 4 + 1][rowA0] = ra0.y;
    As[0][qa * 4 + 2][rowA0] = ra0.z;
    As[0][qa * 4 + 3][rowA0] = ra0.w;
    As[0][qa * 4 + 0][rowA1] = ra1.x;
    As[0][qa * 4 + 1][rowA1] = ra1.y;
    As[0][qa * 4 + 2][rowA1] = ra1.z;
    As[0][qa * 4 + 3][rowA1] = ra1.w;
    *(float4*)&Bs[0][krB][nqB * 4] = rb0;
    *(float4*)&Bs[0][krB + 8][nqB * 4] = rb1;
    __syncthreads();

    int buf = 0;
    for (int k0 = 0; k0 < K; k0 += 16) {
        const bool more = (k0 + 16 < K);
        if (more) {
            ra0 = *(const float4*)(Xr0 + k0 + 16);
            ra1 = *(const float4*)(Xr1 + k0 + 16);
            rb0 = *(const float4*)(Wp0 + (size_t)(k0 + 16) * G3);
            rb1 = *(const float4*)(Wp1 + (size_t)(k0 + 16) * G3);
        }
#pragma unroll
        for (int kk = 0; kk < 16; kk++) {
            float4 av0 = *(const float4*)&As[buf][kk][ty * 8];
            float4 av1 = *(const float4*)&As[buf][kk][ty * 8 + 4];
            float4 bv0 = *(const float4*)&Bs[buf][kk][tx * 4];        // 256B span: 2-way
            float4 bv1 = *(const float4*)&Bs[buf][kk][tx * 4 + 64];   // 256B span: 2-way
            float aa[8] = {av0.x, av0.y, av0.z, av0.w, av1.x, av1.y, av1.z, av1.w};
            float2 bb[4] = {make_float2(bv0.x, bv0.y), make_float2(bv0.z, bv0.w),
                            make_float2(bv1.x, bv1.y), make_float2(bv1.z, bv1.w)};
#pragma unroll
            for (int i = 0; i < 8; i++) {
                float2 a2 = make_float2(aa[i], aa[i]);
#pragma unroll
                for (int j = 0; j < 4; j++) acc[i][j] = ffma2(a2, bb[j], acc[i][j]);
            }
        }
        if (more) {
            int nb = buf ^ 1;
            As[nb][qa * 4 + 0][rowA0] = ra0.x;
            As[nb][qa * 4 + 1][rowA0] = ra0.y;
            As[nb][qa * 4 + 2][rowA0] = ra0.z;
            As[nb][qa * 4 + 3][rowA0] = ra0.w;
            As[nb][qa * 4 + 0][rowA1] = ra1.x;
            As[nb][qa * 4 + 1][rowA1] = ra1.y;
            As[nb][qa * 4 + 2][rowA1] = ra1.z;
            As[nb][qa * 4 + 3][rowA1] = ra1.w;
            *(float4*)&Bs[nb][krB][nqB * 4] = rb0;
            *(float4*)&Bs[nb][krB + 8][nqB * 4] = rb1;
            __syncthreads();
            buf = nb;
        }
    }

    float4 bsv0 = *(const float4*)(bias + bn + tx * 4);
    float4 bsv1 = *(const float4*)(bias + bn + 64 + tx * 4);
    float bv[8] = {bsv0.x, bsv0.y, bsv0.z, bsv0.w, bsv1.x, bsv1.y, bsv1.z, bsv1.w};
#pragma unroll
    for (int i = 0; i < 8; i++) {
        int m2 = bm + ty * 8 + i;
        float* crow = C + (size_t)m2 * G3 + bn;
        float4 v0 = make_float4(acc[i][0].x + bv[0], acc[i][0].y + bv[1],
                                acc[i][1].x + bv[2], acc[i][1].y + bv[3]);
        float4 v1 = make_float4(acc[i][2].x + bv[4], acc[i][2].y + bv[5],
                                acc[i][3].x + bv[6], acc[i][3].y + bv[7]);
        *(float4*)(crow + tx * 4) = v0;
        *(float4*)(crow + 64 + tx * 4) = v1;
    }
}

// ---------------- persistent recurrent layer (cp.async staged h, group barriers) ----------------
__global__ __launch_bounds__(512, 1) void gru_layer(
    int layer, const float* __restrict__ bhh_f, const float* __restrict__ bhh_b)
{
    extern __shared__ float smem[];
    float* wsm  = smem;
    float2* red = (float2*)(smem + W_SM_FLOATS);   // overlays h staging (disjoint in time)

    const int dir  = blockIdx.y;
    const int jblk = blockIdx.x;
    const int tid  = threadIdx.x;
    const int kg   = tid >> 6;
    const int t64  = tid & 63;
    const int bg   = t64 >> 3;
    const int jp   = t64 & 7;
    const int j0   = jblk * 16 + jp * 2;
    const int b0   = bg * 4;
    const int gbar = kg + 1;            // named barrier id for this 64-thread group

    const float* wsrc = g_whh_p[layer][dir] + (size_t)jblk * W_SM_FLOATS;
    for (int i = tid; i < W_SM_FLOATS / 4; i += 512)
        ((float4*)wsm)[i] = ((const float4*)wsrc)[i];

    const float* bhh = dir ? bhh_b : bhh_f;
    const float2 br  = *(const float2*)(bhh + j0);
    const float2 bz  = *(const float2*)(bhh + HH + j0);
    const float2 bn2 = *(const float2*)(bhh + 2 * HH + j0);
    const float* gx_base = g_gx[dir];

    float* hst_grp = smem + W_SM_FLOATS + kg * 1024;
    const unsigned hstg = (unsigned)__cvta_generic_to_shared(hst_grp);
    __syncthreads();

    for (int t = 0; t < SS; t++) {
        const float* hprev = g_h[dir][t & 1];
        const int s_sel = dir ? (SS - 1 - t) : t;
        const float* hsrc = hprev + kg * 128 * BB;

        // prologue: stage chunks 0, 1
#pragma unroll
        for (int pc = 0; pc < 2; pc++) {
            unsigned dst = hstg + pc * 2048 + t64 * 16;
            const float* src = hsrc + pc * 512 + t64 * 4;
            cpasync16(dst, src);
            cpasync16(dst + 1024, src + 256);
            asm volatile("cp.async.commit_group;" ::: "memory");
        }

        float2 xr[4], xz[4], xn[4];
        float4 hpa, hpb;
        if (kg == 0) {
#pragma unroll
            for (int bi = 0; bi < 4; bi++) {
                const float* gxp = gx_base + ((size_t)s_sel * BB + b0 + bi) * G3 + j0;
                xr[bi] = ldcg2(gxp);
                xz[bi] = ldcg2(gxp + HH);
                xn[bi] = ldcg2(gxp + 2 * HH);
            }
            hpa = ldcg4(hprev + j0 * BB + b0);
            hpb = ldcg4(hprev + (j0 + 1) * BB + b0);
        }

        float2 ar[4], az[4], an[4];
#pragma unroll
        for (int bi = 0; bi < 4; bi++) {
            ar[bi] = make_float2(0.f, 0.f);
            az[bi] = make_float2(0.f, 0.f);
            an[bi] = make_float2(0.f, 0.f);
        }

#pragma unroll
        for (int c = 0; c < 8; c++) {
            if (c < 7) asm volatile("cp.async.wait_group 1;" ::: "memory");
            else       asm volatile("cp.async.wait_group 0;" ::: "memory");
            GROUP_BAR(gbar);            // group's chunk fully staged
            const float* hst = hst_grp + (c & 1) * 512;
            const float* wq  = wsm + (size_t)(kg * 128 + c * 16) * 48 + jp * 2;
#pragma unroll 4
            for (int kl = 0; kl < 16; kl++) {
                float4 h4 = *(const float4*)&hst[kl * 32 + b0];
                const float* w = wq + kl * 48;
                float2 wr = *(const float2*)(w);
                float2 wz = *(const float2*)(w + 16);
                float2 wn = *(const float2*)(w + 32);
                ar[0] = ffma2(bcast2(h4.x), wr, ar[0]);
                az[0] = ffma2(bcast2(h4.x), wz, az[0]);
                an[0] = ffma2(bcast2(h4.x), wn, an[0]);
                ar[1] = ffma2(bcast2(h4.y), wr, ar[1]);
                az[1] = ffma2(bcast2(h4.y), wz, az[1]);
                an[1] = ffma2(bcast2(h4.y), wn, an[1]);
                ar[2] = ffma2(bcast2(h4.z), wr, ar[2]);
                az[2] = ffma2(bcast2(h4.z), wz, az[2]);
                an[2] = ffma2(bcast2(h4.z), wn, an[2]);
                ar[3] = ffma2(bcast2(h4.w), wr, ar[3]);
                az[3] = ffma2(bcast2(h4.w), wz, az[3]);
                an[3] = ffma2(bcast2(h4.w), wn, an[3]);
            }
            GROUP_BAR(gbar);            // group's reads done before re-staging buffer
            if (c + 2 < 8) {
                unsigned dst = hstg + (c & 1) * 2048 + t64 * 16;
                const float* src = hsrc + (c + 2) * 512 + t64 * 4;
                cpasync16(dst, src);
                cpasync16(dst + 1024, src + 256);
                asm volatile("cp.async.commit_group;" ::: "memory");
            }
        }

        // k-split reduction 8->4->2->1 (full syncs: red overlays other groups' staging)
        __syncthreads();
        if (kg >= 4) {
            int base = (kg - 4) * 768;
#pragma unroll
            for (int bi = 0; bi < 4; bi++) {
                red[base + (bi * 3 + 0) * 64 + t64] = ar[bi];
                red[base + (bi * 3 + 1) * 64 + t64] = az[bi];
                red[base + (bi * 3 + 2) * 64 + t64] = an[bi];
            }
        }
        __syncthreads();
        if (kg < 4) {
            int base = kg * 768;
#pragma unroll
            for (int bi = 0; bi < 4; bi++) {
                float2 vr = red[base + (bi * 3 + 0) * 64 + t64];
                float2 vz = red[base + (bi * 3 + 1) * 64 + t64];
                float2 vn = red[base + (bi * 3 + 2) * 64 + t64];
                ar[bi].x += vr.x; ar[bi].y += vr.y;
                az[bi].x += vz.x; az[bi].y += vz.y;
                an[bi].x += vn.x; an[bi].y += vn.y;
            }
        }
        __syncthreads();
        if (kg == 2 || kg == 3) {
            int base = (kg - 2) * 768;
#pragma unroll
            for (int bi = 0; bi < 4; bi++) {
                red[base + (bi * 3 + 0) * 64 + t64] = ar[bi];
                red[base + (bi * 3 + 1) * 64 + t64] = az[bi];
                red[base + (bi * 3 + 2) * 64 + t64] = an[bi];
            }
        }
        __syncthreads();
        if (kg < 2) {
            int base = kg * 768;
#pragma unroll
            for (int bi = 0; bi < 4; bi++) {
                float2 vr = red[base + (bi * 3 + 0) * 64 + t64];
                float2 vz = red[base + (bi * 3 + 1) * 64 + t64];
                float2 vn = red[base + (bi * 3 + 2) * 64 + t64];
                ar[bi].x += vr.x; ar[bi].y += vr.y;
                az[bi].x += vz.x; az[bi].y += vz.y;
                an[bi].x += vn.x; an[bi].y += vn.y;
            }
        }
        __syncthreads();
        if (kg == 1) {
#pragma unroll
            for (int bi = 0; bi < 4; bi++) {
                red[(bi * 3 + 0) * 64 + t64] = ar[bi];
                red[(bi * 3 + 1) * 64 + t64] = az[bi];
                red[(bi * 3 + 2) * 64 + t64] = an[bi];
            }
        }
        __syncthreads();
        if (kg == 0) {
            float h0n[4], h1n[4];
#pragma unroll
            for (int bi = 0; bi < 4; bi++) {
                float2 vr = red[(bi * 3 + 0) * 64 + t64];
                float2 vz = red[(bi * 3 + 1) * 64 + t64];
                float2 vn = red[(bi * 3 + 2) * 64 + t64];
                float sr0 = xr[bi].x + ar[bi].x + vr.x + br.x;
                float sr1 = xr[bi].y + ar[bi].y + vr.y + br.y;
                float sz0 = xz[bi].x + az[bi].x + vz.x + bz.x;
                float sz1 = xz[bi].y + az[bi].y + vz.y + bz.y;
                float sn0 = an[bi].x + vn.x + bn2.x;
                float sn1 = an[bi].y + vn.y + bn2.y;
                float r0 = sigmoidf_(sr0), r1 = sigmoidf_(sr1);
                float z0 = sigmoidf_(sz0), z1 = sigmoidf_(sz1);
                float n0 = tanhf(xn[bi].x + r0 * sn0);
                float n1 = tanhf(xn[bi].y + r1 * sn1);
                float hp0 = (bi == 0) ? hpa.x : (bi == 1) ? hpa.y : (bi == 2) ? hpa.z : hpa.w;
                float hp1 = (bi == 0) ? hpb.x : (bi == 1) ? hpb.y : (bi == 2) ? hpb.z : hpb.w;
                h0n[bi] = (1.f - z0) * n0 + z0 * hp0;
                h1n[bi] = (1.f - z1) * n1 + z1 * hp1;
            }
            float* hout = g_h[dir][(t + 1) & 1];
            *(float4*)(hout + j0 * BB + b0) = make_float4(h0n[0], h0n[1], h0n[2], h0n[3]);
            *(float4*)(hout + (j0 + 1) * BB + b0) = make_float4(h1n[0], h1n[1], h1n[2], h1n[3]);
            if (layer == 0) {
#pragma unroll
                for (int bi = 0; bi < 4; bi++)
                    *(float2*)(&g_out0[((size_t)(b0 + bi) * SS + s_sel) * H2 + dir * HH + j0]) =
                        make_float2(h0n[bi], h1n[bi]);
            }
        }

        dir_barrier(dir, (unsigned)(t + 1));
    }
}

// ---------------- zero hidden + barrier state (between layers) ----------------
__global__ void zero_h_k() {
    int i = blockIdx.x * blockDim.x + threadIdx.x;
    if (i < HH * BB) { g_h[0][0][i] = 0.f; g_h[1][0][i] = 0.f; }
    if (i < 128) g_bar_flags[i >> 6][i & 63] = 0u;
}

// ---------------- final output ----------------
__global__ void finalize_k(float* __restrict__ out) {
    int i = blockIdx.x * blockDim.x + threadIdx.x;
    if (i < BB * H2) {
        int b = i >> 11, c = i & 2047;
        out[i] = (c < HH) ? g_h[0][0][c * BB + b] : g_h[1][0][(c - HH) * BB + b];
    }
}

// ---------------- host ----------------
extern "C" void kernel_launch(void* const* d_in, const int* in_sizes, int n_in,
                              void* d_out, int out_size)
{
    const float* x       = (const float*)d_in[0];
    const float* w_ih_f0 = (const float*)d_in[1];
    const float* w_hh_f0 = (const float*)d_in[2];
    const float* b_ih_f0 = (const float*)d_in[3];
    const float* b_hh_f0 = (const float*)d_in[4];
    const float* w_ih_b0 = (const float*)d_in[5];
    const float* w_hh_b0 = (const float*)d_in[6];
    const float* b_ih_b0 = (const float*)d_in[7];
    const float* b_hh_b0 = (const float*)d_in[8];
    const float* w_ih_f1 = (const float*)d_in[9];
    const float* w_hh_f1 = (const float*)d_in[10];
    const float* b_ih_f1 = (const float*)d_in[11];
    const float* b_hh_f1 = (const float*)d_in[12];
    const float* w_ih_b1 = (const float*)d_in[13];
    const float* w_hh_b1 = (const float*)d_in[14];
    const float* b_ih_b1 = (const float*)d_in[15];
    const float* b_hh_b1 = (const float*)d_in[16];
    float* out = (float*)d_out;

    cudaFuncSetAttribute(gru_layer, cudaFuncAttributeMaxDynamicSharedMemorySize,
                         GRU_SMEM_BYTES);

    float *wih0, *wih1, *gx, *out0;
    cudaGetSymbolAddress((void**)&wih0, g_wih0_t);
    cudaGetSymbolAddress((void**)&wih1, g_wih1_t);
    cudaGetSymbolAddress((void**)&gx,   g_gx);
    cudaGetSymbolAddress((void**)&out0, g_out0);

    float* wih0_f = wih0;
    float* wih0_b = wih0 + (size_t)II * G3;
    float* wih1_f = wih1;
    float* wih1_b = wih1 + (size_t)H2 * G3;
    float* gx_f = gx;
    float* gx_b = gx + (size_t)BB * SS * G3;

    dim3 ggrid(G3 / 128, (BB * SS) / 128, 2);

    transpose_ih<<<dim3(96, 64, 4), dim3(32, 8)>>>(
        w_ih_f0, w_ih_b0, w_ih_f1, w_ih_b1, wih0_f, wih0_b, wih1_f, wih1_b);
    prepack_whh<<<dim3(12288, 4), 256>>>(w_hh_f0, w_hh_b0, w_hh_f1, w_hh_b1);
    gemm_gx2<<<ggrid, 256>>>(x, SS * II, II, II, wih0_f, wih0_b,
                             b_ih_f0, b_ih_b0, gx_f, gx_b);
    gru_layer<<<dim3(64, 2), 512, GRU_SMEM_BYTES>>>(0, b_hh_f0, b_hh_b0);

    gemm_gx2<<<ggrid, 256>>>(out0, SS * H2, H2, H2, wih1_f, wih1_b,
                             b_ih_f1, b_ih_b1, gx_f, gx_b);
    zero_h_k<<<(HH * BB + 255) / 256, 256>>>();
    gru_layer<<<dim3(64, 2), 512, GRU_SMEM_BYTES>>>(1, b_hh_f1, b_hh_b1);

    finalize_k<<<(BB * H2 + 255) / 256, 256>>>(out);
}

// round 10
// speedup vs baseline: 1.1491x; 1.1491x over previous
#include <cuda_runtime.h>
#include <math.h>

#define BB 32
#define SS 512
#define II 512
#define HH 1024
#define G3 3072
#define H2 2048

#define W_SM_FLOATS (1024 * 48)         // per-CTA W slice: 196,608 B
#define HSTAGE_FLOATS (8 * 2 * 512)     // 8 groups x 2 bufs x (16k x 32b) = 32 KB
#define GRU_SMEM_BYTES ((W_SM_FLOATS + HSTAGE_FLOATS) * 4)   // 229,376 B

// ---------------- device scratch ----------------
__device__ float g_wih0_t[2][II * G3];
__device__ float g_wih1_t[2][(size_t)H2 * G3];
__device__ float g_whh_p[2][2][HH * G3];
__device__ float g_gx[2][(size_t)BB * SS * G3];
__device__ float g_h[2][2][HH * BB];            // [dir][parity][j][b]
__device__ float g_out0[(size_t)BB * SS * H2];
__device__ unsigned g_bar_count[2];
__device__ unsigned g_bar_gen[2];

// ---------------- helpers ----------------
__device__ __forceinline__ float2 ffma2(float2 a, float2 b, float2 c) {
    unsigned long long A = *reinterpret_cast<unsigned long long*>(&a);
    unsigned long long B = *reinterpret_cast<unsigned long long*>(&b);
    unsigned long long C = *reinterpret_cast<unsigned long long*>(&c);
    unsigned long long D;
    asm("fma.rn.f32x2 %0, %1, %2, %3;" : "=l"(D) : "l"(A), "l"(B), "l"(C));
    return *reinterpret_cast<float2*>(&D);
}
__device__ __forceinline__ float2 bcast2(float x) { return make_float2(x, x); }
__device__ __forceinline__ float sigmoidf_(float x) { return 1.0f / (1.0f + expf(-x)); }

__device__ __forceinline__ float4 ldcg4(const float* p) {
    float4 v;
    asm volatile("ld.global.cg.v4.f32 {%0,%1,%2,%3}, [%4];"
                 : "=f"(v.x), "=f"(v.y), "=f"(v.z), "=f"(v.w) : "l"(p));
    return v;
}
__device__ __forceinline__ float2 ldcg2(const float* p) {
    float2 v;
    asm volatile("ld.global.cg.v2.f32 {%0,%1}, [%2];" : "=f"(v.x), "=f"(v.y) : "l"(p));
    return v;
}
__device__ __forceinline__ void cpasync16(unsigned dst, const float* src) {
    asm volatile("cp.async.cg.shared.global [%0], [%1], 16;" :: "r"(dst), "l"(src) : "memory");
}

// grid barrier per direction (64 CTAs), monotonic generation (single-line broadcast poll)
__device__ __forceinline__ void dir_barrier(int dir, unsigned n) {
    __syncthreads();
    if (threadIdx.x == 0) {
        unsigned* cnt = &g_bar_count[dir];
        unsigned* gen = &g_bar_gen[dir];
        unsigned old;
        asm volatile("atom.acq_rel.gpu.global.add.u32 %0, [%1], 1;"
                     : "=r"(old) : "l"(cnt) : "memory");
        if (old == n * 64u - 1u) {
            asm volatile("red.release.gpu.global.add.u32 [%0], 1;" :: "l"(gen) : "memory");
        } else {
            unsigned cur;
            do {
                __nanosleep(16);
                asm volatile("ld.acquire.gpu.global.u32 %0, [%1];"
                             : "=r"(cur) : "l"(gen) : "memory");
            } while (cur < n);
        }
    }
    __syncthreads();
}

// ---------------- batched transpose for w_ih: in[3072][K] -> out[K][3072] ----------------
__global__ void transpose_ih(const float* f0, const float* b0,
                             const float* f1, const float* b1,
                             float* df0, float* db0, float* df1, float* db1) {
    __shared__ float tile[32][33];
    const float* in; float* out; int K;
    switch (blockIdx.z) {
        case 0: in = f0; out = df0; K = II; break;
        case 1: in = b0; out = db0; K = II; break;
        case 2: in = f1; out = df1; K = H2; break;
        default: in = b1; out = db1; K = H2; break;
    }
    int n0 = blockIdx.x * 32, k0 = blockIdx.y * 32;
    if (k0 >= K) return;
    for (int i = threadIdx.y; i < 32; i += 8)
        tile[i][threadIdx.x] = in[(size_t)(n0 + i) * K + k0 + threadIdx.x];
    __syncthreads();
    for (int i = threadIdx.y; i < 32; i += 8)
        out[(size_t)(k0 + i) * G3 + n0 + threadIdx.x] = tile[threadIdx.x][i];
}

// ---------------- prepack W_hh into [jblk][k][g][jp][c] + zero h / barriers ----------------
__global__ void prepack_whh(const float* w00, const float* w01,
                            const float* w10, const float* w11) {
    int mat = blockIdx.y;
    const float* src = (mat == 0) ? w00 : (mat == 1) ? w01 : (mat == 2) ? w10 : w11;
    float* dst = g_whh_p[mat >> 1][mat & 1];
    int idx = blockIdx.x * 256 + threadIdx.x;   // n*1024 + k
    int k = idx & 1023;
    int n = idx >> 10;
    int g = n >> 10;
    int nj = n & 1023;
    int jblk = nj >> 4;
    int jp = (nj >> 1) & 7;
    int c  = nj & 1;
    dst[jblk * W_SM_FLOATS + k * 48 + g * 16 + jp * 2 + c] = src[idx];
    if (mat == 0) {
        if (idx < HH * BB) { g_h[0][0][idx] = 0.f; g_h[1][0][idx] = 0.f; }
        if (idx < 2) { g_bar_count[idx] = 0u; g_bar_gen[idx] = 0u; }
    }
}

// ---------------- SGEMM 128x128x16, double-buffered, conflict-light B reads ----------------
__global__ __launch_bounds__(256, 2) void gemm_gx2(
    const float* __restrict__ X, int strideB, int strideS, int K,
    const float* __restrict__ Wt0, const float* __restrict__ Wt1,
    const float* __restrict__ bias0, const float* __restrict__ bias1,
    float* __restrict__ C0, float* __restrict__ C1)
{
    __shared__ float As[2][16][128];
    __shared__ float Bs[2][16][128];
    const float* Wt   = blockIdx.z ? Wt1 : Wt0;
    const float* bias = blockIdx.z ? bias1 : bias0;
    float* C          = blockIdx.z ? C1 : C0;

    const int tid = threadIdx.x;
    const int bn = blockIdx.x * 128;
    const int bm = blockIdx.y * 128;
    const int tx = tid & 15, ty = tid >> 4;

    const int rowA0 = tid >> 2;
    const int rowA1 = rowA0 + 64;
    const int qa = tid & 3;
    int m0 = bm + rowA0, m1 = bm + rowA1;
    const float* Xr0 = X + (size_t)(m0 & 31) * strideB + (size_t)(m0 >> 5) * strideS + qa * 4;
    const float* Xr1 = X + (size_t)(m1 & 31) * strideB + (size_t)(m1 >> 5) * strideS + qa * 4;
    const int krB = tid >> 5;
    const int nqB = tid & 31;
    const float* Wp0 = Wt + (size_t)krB * G3 + bn + nqB * 4;
    const float* Wp1 = Wt + (size_t)(krB + 8) * G3 + bn + nqB * 4;

    float2 acc[8][4];
#pragma unroll
    for (int i = 0; i < 8; i++)
#pragma unroll
        for (int j = 0; j < 4; j++) acc[i][j] = make_float2(0.f, 0.f);

    float4 ra0 = *(const float4*)(Xr0);
    float4 ra1 = *(const float4*)(Xr1);
    float4 rb0 = *(const float4*)(Wp0);
    float4 rb1 = *(const float4*)(Wp1);
    As[0][qa * 4 + 0][rowA0] = ra0.x;
    As[0][qa * 4 + 1][rowA0] = ra0.y;
    As[0][qa * 4 + 2][rowA0] = ra0.z;
    As[0][qa * 4 + 3][rowA0] = ra0.w;
    As[0][qa * 4 + 0][rowA1] = ra1.x;
    As[0][qa * 4 + 1][rowA1] = ra1.y;
    As[0][qa * 4 + 2][rowA1] = ra1.z;
    As[0][qa * 4 + 3][rowA1] = ra1.w;
    *(float4*)&Bs[0][krB][nqB * 4] = rb0;
    *(float4*)&Bs[0][krB + 8][nqB * 4] = rb1;
    __syncthreads();

    int buf = 0;
    for (int k0 = 0; k0 < K; k0 += 16) {
        const bool more = (k0 + 16 < K);
        if (more) {
            ra0 = *(const float4*)(Xr0 + k0 + 16);
            ra1 = *(const float4*)(Xr1 + k0 + 16);
            rb0 = *(const float4*)(Wp0 + (size_t)(k0 + 16) * G3);
            rb1 = *(const float4*)(Wp1 + (size_t)(k0 + 16) * G3);
        }
#pragma unroll
        for (int kk = 0; kk < 16; kk++) {
            float4 av0 = *(const float4*)&As[buf][kk][ty * 8];
            float4 av1 = *(const float4*)&As[buf][kk][ty * 8 + 4];
            float4 bv0 = *(const float4*)&Bs[buf][kk][tx * 4];        // 256B span: 2-way
            float4 bv1 = *(const float4*)&Bs[buf][kk][tx * 4 + 64];   // 256B span: 2-way
            float aa[8] = {av0.x, av0.y, av0.z, av0.w, av1.x, av1.y, av1.z, av1.w};
            float2 bb[4] = {make_float2(bv0.x, bv0.y), make_float2(bv0.z, bv0.w),
                            make_float2(bv1.x, bv1.y), make_float2(bv1.z, bv1.w)};
#pragma unroll
            for (int i = 0; i < 8; i++) {
                float2 a2 = make_float2(aa[i], aa[i]);
#pragma unroll
                for (int j = 0; j < 4; j++) acc[i][j] = ffma2(a2, bb[j], acc[i][j]);
            }
        }
        if (more) {
            int nb = buf ^ 1;
            As[nb][qa * 4 + 0][rowA0] = ra0.x;
            As[nb][qa * 4 + 1][rowA0] = ra0.y;
            As[nb][qa * 4 + 2][rowA0] = ra0.z;
            As[nb][qa * 4 + 3][rowA0] = ra0.w;
            As[nb][qa * 4 + 0][rowA1] = ra1.x;
            As[nb][qa * 4 + 1][rowA1] = ra1.y;
            As[nb][qa * 4 + 2][rowA1] = ra1.z;
            As[nb][qa * 4 + 3][rowA1] = ra1.w;
            *(float4*)&Bs[nb][krB][nqB * 4] = rb0;
            *(float4*)&Bs[nb][krB + 8][nqB * 4] = rb1;
            __syncthreads();
            buf = nb;
        }
    }

    float4 bsv0 = *(const float4*)(bias + bn + tx * 4);
    float4 bsv1 = *(const float4*)(bias + bn + 64 + tx * 4);
    float bv[8] = {bsv0.x, bsv0.y, bsv0.z, bsv0.w, bsv1.x, bsv1.y, bsv1.z, bsv1.w};
#pragma unroll
    for (int i = 0; i < 8; i++) {
        int m2 = bm + ty * 8 + i;
        float* crow = C + (size_t)m2 * G3 + bn;
        float4 v0 = make_float4(acc[i][0].x + bv[0], acc[i][0].y + bv[1],
                                acc[i][1].x + bv[2], acc[i][1].y + bv[3]);
        float4 v1 = make_float4(acc[i][2].x + bv[4], acc[i][2].y + bv[5],
                                acc[i][3].x + bv[6], acc[i][3].y + bv[7]);
        *(float4*)(crow + tx * 4) = v0;
        *(float4*)(crow + 64 + tx * 4) = v1;
    }
}

// ---------------- persistent recurrent layer (cp.async staged h) — R8 version ----------------
__global__ __launch_bounds__(512, 1) void gru_layer(
    int layer, const float* __restrict__ bhh_f, const float* __restrict__ bhh_b)
{
    extern __shared__ float smem[];
    float* wsm  = smem;
    float2* red = (float2*)(smem + W_SM_FLOATS);   // overlays h staging (disjoint in time)

    const int dir  = blockIdx.y;
    const int jblk = blockIdx.x;
    const int tid  = threadIdx.x;
    const int kg   = tid >> 6;
    const int t64  = tid & 63;
    const int bg   = t64 >> 3;
    const int jp   = t64 & 7;
    const int j0   = jblk * 16 + jp * 2;
    const int b0   = bg * 4;

    const float* wsrc = g_whh_p[layer][dir] + (size_t)jblk * W_SM_FLOATS;
    for (int i = tid; i < W_SM_FLOATS / 4; i += 512)
        ((float4*)wsm)[i] = ((const float4*)wsrc)[i];

    const float* bhh = dir ? bhh_b : bhh_f;
    const float2 br  = *(const float2*)(bhh + j0);
    const float2 bz  = *(const float2*)(bhh + HH + j0);
    const float2 bn2 = *(const float2*)(bhh + 2 * HH + j0);
    const float* gx_base = g_gx[dir];

    float* hst_grp = smem + W_SM_FLOATS + kg * 1024;
    const unsigned hstg = (unsigned)__cvta_generic_to_shared(hst_grp);
    __syncthreads();

    for (int t = 0; t < SS; t++) {
        const float* hprev = g_h[dir][t & 1];
        const int s_sel = dir ? (SS - 1 - t) : t;
        const float* hsrc = hprev + kg * 128 * BB;

        // prologue: stage chunks 0, 1
#pragma unroll
        for (int pc = 0; pc < 2; pc++) {
            unsigned dst = hstg + pc * 2048 + t64 * 16;
            const float* src = hsrc + pc * 512 + t64 * 4;
            cpasync16(dst, src);
            cpasync16(dst + 1024, src + 256);
            asm volatile("cp.async.commit_group;" ::: "memory");
        }

        float2 xr[4], xz[4], xn[4];
        float4 hpa, hpb;
        if (kg == 0) {
#pragma unroll
            for (int bi = 0; bi < 4; bi++) {
                const float* gxp = gx_base + ((size_t)s_sel * BB + b0 + bi) * G3 + j0;
                xr[bi] = ldcg2(gxp);
                xz[bi] = ldcg2(gxp + HH);
                xn[bi] = ldcg2(gxp + 2 * HH);
            }
            hpa = ldcg4(hprev + j0 * BB + b0);
            hpb = ldcg4(hprev + (j0 + 1) * BB + b0);
        }

        float2 ar[4], az[4], an[4];
#pragma unroll
        for (int bi = 0; bi < 4; bi++) {
            ar[bi] = make_float2(0.f, 0.f);
            az[bi] = make_float2(0.f, 0.f);
            an[bi] = make_float2(0.f, 0.f);
        }

#pragma unroll
        for (int c = 0; c < 8; c++) {
            if (c < 7) asm volatile("cp.async.wait_group 1;" ::: "memory");
            else       asm volatile("cp.async.wait_group 0;" ::: "memory");
            __syncthreads();
            const float* hst = hst_grp + (c & 1) * 512;
            const float* wq  = wsm + (size_t)(kg * 128 + c * 16) * 48 + jp * 2;
#pragma unroll 4
            for (int kl = 0; kl < 16; kl++) {
                float4 h4 = *(const float4*)&hst[kl * 32 + b0];
                const float* w = wq + kl * 48;
                float2 wr = *(const float2*)(w);
                float2 wz = *(const float2*)(w + 16);
                float2 wn = *(const float2*)(w + 32);
                ar[0] = ffma2(bcast2(h4.x), wr, ar[0]);
                az[0] = ffma2(bcast2(h4.x), wz, az[0]);
                an[0] = ffma2(bcast2(h4.x), wn, an[0]);
                ar[1] = ffma2(bcast2(h4.y), wr, ar[1]);
                az[1] = ffma2(bcast2(h4.y), wz, az[1]);
                an[1] = ffma2(bcast2(h4.y), wn, an[1]);
                ar[2] = ffma2(bcast2(h4.z), wr, ar[2]);
                az[2] = ffma2(bcast2(h4.z), wz, az[2]);
                an[2] = ffma2(bcast2(h4.z), wn, an[2]);
                ar[3] = ffma2(bcast2(h4.w), wr, ar[3]);
                az[3] = ffma2(bcast2(h4.w), wz, az[3]);
                an[3] = ffma2(bcast2(h4.w), wn, an[3]);
            }
            __syncthreads();
            if (c + 2 < 8) {
                unsigned dst = hstg + (c & 1) * 2048 + t64 * 16;
                const float* src = hsrc + (c + 2) * 512 + t64 * 4;
                cpasync16(dst, src);
                cpasync16(dst + 1024, src + 256);
                asm volatile("cp.async.commit_group;" ::: "memory");
            }
        }

        // k-split reduction 8->4->2->1
        __syncthreads();
        if (kg >= 4) {
            int base = (kg - 4) * 768;
#pragma unroll
            for (int bi = 0; bi < 4; bi++) {
                red[base + (bi * 3 + 0) * 64 + t64] = ar[bi];
                red[base + (bi * 3 + 1) * 64 + t64] = az[bi];
                red[base + (bi * 3 + 2) * 64 + t64] = an[bi];
            }
        }
        __syncthreads();
        if (kg < 4) {
            int base = kg * 768;
#pragma unroll
            for (int bi = 0; bi < 4; bi++) {
                float2 vr = red[base + (bi * 3 + 0) * 64 + t64];
                float2 vz = red[base + (bi * 3 + 1) * 64 + t64];
                float2 vn = red[base + (bi * 3 + 2) * 64 + t64];
                ar[bi].x += vr.x; ar[bi].y += vr.y;
                az[bi].x += vz.x; az[bi].y += vz.y;
                an[bi].x += vn.x; an[bi].y += vn.y;
            }
        }
        __syncthreads();
        if (kg == 2 || kg == 3) {
            int base = (kg - 2) * 768;
#pragma unroll
            for (int bi = 0; bi < 4; bi++) {
                red[base + (bi * 3 + 0) * 64 + t64] = ar[bi];
                red[base + (bi * 3 + 1) * 64 + t64] = az[bi];
                red[base + (bi * 3 + 2) * 64 + t64] = an[bi];
            }
        }
        __syncthreads();
        if (kg < 2) {
            int base = kg * 768;
#pragma unroll
            for (int bi = 0; bi < 4; bi++) {
                float2 vr = red[base + (bi * 3 + 0) * 64 + t64];
                float2 vz = red[base + (bi * 3 + 1) * 64 + t64];
                float2 vn = red[base + (bi * 3 + 2) * 64 + t64];
                ar[bi].x += vr.x; ar[bi].y += vr.y;
                az[bi].x += vz.x; az[bi].y += vz.y;
                an[bi].x += vn.x; an[bi].y += vn.y;
            }
        }
        __syncthreads();
        if (kg == 1) {
#pragma unroll
            for (int bi = 0; bi < 4; bi++) {
                red[(bi * 3 + 0) * 64 + t64] = ar[bi];
                red[(bi * 3 + 1) * 64 + t64] = az[bi];
                red[(bi * 3 + 2) * 64 + t64] = an[bi];
            }
        }
        __syncthreads();
        if (kg == 0) {
            float h0n[4], h1n[4];
#pragma unroll
            for (int bi = 0; bi < 4; bi++) {
                float2 vr = red[(bi * 3 + 0) * 64 + t64];
                float2 vz = red[(bi * 3 + 1) * 64 + t64];
                float2 vn = red[(bi * 3 + 2) * 64 + t64];
                float sr0 = xr[bi].x + ar[bi].x + vr.x + br.x;
                float sr1 = xr[bi].y + ar[bi].y + vr.y + br.y;
                float sz0 = xz[bi].x + az[bi].x + vz.x + bz.x;
                float sz1 = xz[bi].y + az[bi].y + vz.y + bz.y;
                float sn0 = an[bi].x + vn.x + bn2.x;
                float sn1 = an[bi].y + vn.y + bn2.y;
                float r0 = sigmoidf_(sr0), r1 = sigmoidf_(sr1);
                float z0 = sigmoidf_(sz0), z1 = sigmoidf_(sz1);
                float n0 = tanhf(xn[bi].x + r0 * sn0);
                float n1 = tanhf(xn[bi].y + r1 * sn1);
                float hp0 = (bi == 0) ? hpa.x : (bi == 1) ? hpa.y : (bi == 2) ? hpa.z : hpa.w;
                float hp1 = (bi == 0) ? hpb.x : (bi == 1) ? hpb.y : (bi == 2) ? hpb.z : hpb.w;
                h0n[bi] = (1.f - z0) * n0 + z0 * hp0;
                h1n[bi] = (1.f - z1) * n1 + z1 * hp1;
            }
            float* hout = g_h[dir][(t + 1) & 1];
            *(float4*)(hout + j0 * BB + b0) = make_float4(h0n[0], h0n[1], h0n[2], h0n[3]);
            *(float4*)(hout + (j0 + 1) * BB + b0) = make_float4(h1n[0], h1n[1], h1n[2], h1n[3]);
            if (layer == 0) {
#pragma unroll
                for (int bi = 0; bi < 4; bi++)
                    *(float2*)(&g_out0[((size_t)(b0 + bi) * SS + s_sel) * H2 + dir * HH + j0]) =
                        make_float2(h0n[bi], h1n[bi]);
            }
        }

        dir_barrier(dir, (unsigned)(t + 1));
    }
}

// ---------------- zero hidden + barrier state (between layers) ----------------
__global__ void zero_h_k() {
    int i = blockIdx.x * blockDim.x + threadIdx.x;
    if (i < HH * BB) { g_h[0][0][i] = 0.f; g_h[1][0][i] = 0.f; }
    if (i < 2) { g_bar_count[i] = 0u; g_bar_gen[i] = 0u; }
}

// ---------------- final output ----------------
__global__ void finalize_k(float* __restrict__ out) {
    int i = blockIdx.x * blockDim.x + threadIdx.x;
    if (i < BB * H2) {
        int b = i >> 11, c = i & 2047;
        out[i] = (c < HH) ? g_h[0][0][c * BB + b] : g_h[1][0][(c - HH) * BB + b];
    }
}

// ---------------- host ----------------
extern "C" void kernel_launch(void* const* d_in, const int* in_sizes, int n_in,
                              void* d_out, int out_size)
{
    const float* x       = (const float*)d_in[0];
    const float* w_ih_f0 = (const float*)d_in[1];
    const float* w_hh_f0 = (const float*)d_in[2];
    const float* b_ih_f0 = (const float*)d_in[3];
    const float* b_hh_f0 = (const float*)d_in[4];
    const float* w_ih_b0 = (const float*)d_in[5];
    const float* w_hh_b0 = (const float*)d_in[6];
    const float* b_ih_b0 = (const float*)d_in[7];
    const float* b_hh_b0 = (const float*)d_in[8];
    const float* w_ih_f1 = (const float*)d_in[9];
    const float* w_hh_f1 = (const float*)d_in[10];
    const float* b_ih_f1 = (const float*)d_in[11];
    const float* b_hh_f1 = (const float*)d_in[12];
    const float* w_ih_b1 = (const float*)d_in[13];
    const float* w_hh_b1 = (const float*)d_in[14];
    const float* b_ih_b1 = (const float*)d_in[15];
    const float* b_hh_b1 = (const float*)d_in[16];
    float* out = (float*)d_out;

    cudaFuncSetAttribute(gru_layer, cudaFuncAttributeMaxDynamicSharedMemorySize,
                         GRU_SMEM_BYTES);

    float *wih0, *wih1, *gx, *out0;
    cudaGetSymbolAddress((void**)&wih0, g_wih0_t);
    cudaGetSymbolAddress((void**)&wih1, g_wih1_t);
    cudaGetSymbolAddress((void**)&gx,   g_gx);
    cudaGetSymbolAddress((void**)&out0, g_out0);

    float* wih0_f = wih0;
    float* wih0_b = wih0 + (size_t)II * G3;
    float* wih1_f = wih1;
    float* wih1_b = wih1 + (size_t)H2 * G3;
    float* gx_f = gx;
    float* gx_b = gx + (size_t)BB * SS * G3;

    dim3 ggrid(G3 / 128, (BB * SS) / 128, 2);

    transpose_ih<<<dim3(96, 64, 4), dim3(32, 8)>>>(
        w_ih_f0, w_ih_b0, w_ih_f1, w_ih_b1, wih0_f, wih0_b, wih1_f, wih1_b);
    prepack_whh<<<dim3(12288, 4), 256>>>(w_hh_f0, w_hh_b0, w_hh_f1, w_hh_b1);
    gemm_gx2<<<ggrid, 256>>>(x, SS * II, II, II, wih0_f, wih0_b,
                             b_ih_f0, b_ih_b0, gx_f, gx_b);
    gru_layer<<<dim3(64, 2), 512, GRU_SMEM_BYTES>>>(0, b_hh_f0, b_hh_b0);

    gemm_gx2<<<ggrid, 256>>>(out0, SS * H2, H2, H2, wih1_f, wih1_b,
                             b_ih_f1, b_ih_b1, gx_f, gx_b);
    zero_h_k<<<(HH * BB + 255) / 256, 256>>>();
    gru_layer<<<dim3(64, 2), 512, GRU_SMEM_BYTES>>>(1, b_hh_f1, b_hh_b1);

    finalize_k<<<(BB * H2 + 255) / 256, 256>>>(out);
}

// round 11
// speedup vs baseline: 1.2374x; 1.0769x over previous
#include <cuda_runtime.h>
#include <math.h>

#define BB 32
#define SS 512
#define II 512
#define HH 1024
#define G3 3072
#define H2 2048

#define W_SM_FLOATS (1024 * 48)         // per-CTA W slice: 196,608 B
#define HSTAGE_FLOATS (8 * 2 * 512)     // 8 groups x 2 bufs x (16k x 32b) = 32 KB
#define GRU_SMEM_BYTES ((W_SM_FLOATS + HSTAGE_FLOATS) * 4)   // 229,376 B

// ---------------- device scratch ----------------
__device__ float g_wih0_t[2][II * G3];
__device__ float g_wih1_t[2][(size_t)H2 * G3];
__device__ float g_whh_p[2][2][HH * G3];
__device__ float g_gx[2][(size_t)BB * SS * G3];
__device__ float g_h[2][2][HH * BB];            // [dir][parity][j][b]
__device__ float g_out0[(size_t)BB * SS * H2];
__device__ unsigned g_bar_count[2];

// ---------------- helpers ----------------
__device__ __forceinline__ float2 ffma2(float2 a, float2 b, float2 c) {
    unsigned long long A = *reinterpret_cast<unsigned long long*>(&a);
    unsigned long long B = *reinterpret_cast<unsigned long long*>(&b);
    unsigned long long C = *reinterpret_cast<unsigned long long*>(&c);
    unsigned long long D;
    asm("fma.rn.f32x2 %0, %1, %2, %3;" : "=l"(D) : "l"(A), "l"(B), "l"(C));
    return *reinterpret_cast<float2*>(&D);
}
__device__ __forceinline__ float2 bcast2(float x) { return make_float2(x, x); }

// HW tanh (Blackwell tanh.approx.f32), sigmoid via tanh identity
__device__ __forceinline__ float tanh_fast(float x) {
    float y;
    asm("tanh.approx.f32 %0, %1;" : "=f"(y) : "f"(x));
    return y;
}
__device__ __forceinline__ float sigmoidf_(float x) {
    return fmaf(0.5f, tanh_fast(0.5f * x), 0.5f);
}

__device__ __forceinline__ float4 ldcg4(const float* p) {
    float4 v;
    asm volatile("ld.global.cg.v4.f32 {%0,%1,%2,%3}, [%4];"
                 : "=f"(v.x), "=f"(v.y), "=f"(v.z), "=f"(v.w) : "l"(p));
    return v;
}
__device__ __forceinline__ float2 ldcg2(const float* p) {
    float2 v;
    asm volatile("ld.global.cg.v2.f32 {%0,%1}, [%2];" : "=f"(v.x), "=f"(v.y) : "l"(p));
    return v;
}
__device__ __forceinline__ void cpasync16(unsigned dst, const float* src) {
    asm volatile("cp.async.cg.shared.global [%0], [%1], 16;" :: "r"(dst), "l"(src) : "memory");
}

// grid barrier per direction (64 CTAs): fire-and-forget REDG arrival (no
// atomic return serialization) + single-line broadcast poll on the count.
__device__ __forceinline__ void dir_barrier(int dir, unsigned n) {
    __syncthreads();
    if (threadIdx.x == 0) {
        unsigned* cnt = &g_bar_count[dir];
        asm volatile("red.release.gpu.global.add.u32 [%0], 1;" :: "l"(cnt) : "memory");
        const unsigned target = n * 64u;
        unsigned cur;
        do {
            asm volatile("ld.acquire.gpu.global.u32 %0, [%1];"
                         : "=r"(cur) : "l"(cnt) : "memory");
            if (cur >= target) break;
            __nanosleep(16);
        } while (true);
    }
    __syncthreads();
}

// ---------------- batched transpose for w_ih: in[3072][K] -> out[K][3072] ----------------
__global__ void transpose_ih(const float* f0, const float* b0,
                             const float* f1, const float* b1,
                             float* df0, float* db0, float* df1, float* db1) {
    __shared__ float tile[32][33];
    const float* in; float* out; int K;
    switch (blockIdx.z) {
        case 0: in = f0; out = df0; K = II; break;
        case 1: in = b0; out = db0; K = II; break;
        case 2: in = f1; out = df1; K = H2; break;
        default: in = b1; out = db1; K = H2; break;
    }
    int n0 = blockIdx.x * 32, k0 = blockIdx.y * 32;
    if (k0 >= K) return;
    for (int i = threadIdx.y; i < 32; i += 8)
        tile[i][threadIdx.x] = in[(size_t)(n0 + i) * K + k0 + threadIdx.x];
    __syncthreads();
    for (int i = threadIdx.y; i < 32; i += 8)
        out[(size_t)(k0 + i) * G3 + n0 + threadIdx.x] = tile[threadIdx.x][i];
}

// ---------------- prepack W_hh into [jblk][k][g][jp][c] + zero h / barriers ----------------
__global__ void prepack_whh(const float* w00, const float* w01,
                            const float* w10, const float* w11) {
    int mat = blockIdx.y;
    const float* src = (mat == 0) ? w00 : (mat == 1) ? w01 : (mat == 2) ? w10 : w11;
    float* dst = g_whh_p[mat >> 1][mat & 1];
    int idx = blockIdx.x * 256 + threadIdx.x;   // n*1024 + k
    int k = idx & 1023;
    int n = idx >> 10;
    int g = n >> 10;
    int nj = n & 1023;
    int jblk = nj >> 4;
    int jp = (nj >> 1) & 7;
    int c  = nj & 1;
    dst[jblk * W_SM_FLOATS + k * 48 + g * 16 + jp * 2 + c] = src[idx];
    if (mat == 0) {
        if (idx < HH * BB) { g_h[0][0][idx] = 0.f; g_h[1][0][idx] = 0.f; }
        if (idx < 2) g_bar_count[idx] = 0u;
    }
}

// ---------------- SGEMM 128x128x16, double-buffered, conflict-light B reads ----------------
__global__ __launch_bounds__(256, 2) void gemm_gx2(
    const float* __restrict__ X, int strideB, int strideS, int K,
    const float* __restrict__ Wt0, const float* __restrict__ Wt1,
    const float* __restrict__ bias0, const float* __restrict__ bias1,
    float* __restrict__ C0, float* __restrict__ C1)
{
    __shared__ float As[2][16][128];
    __shared__ float Bs[2][16][128];
    const float* Wt   = blockIdx.z ? Wt1 : Wt0;
    const float* bias = blockIdx.z ? bias1 : bias0;
    float* C          = blockIdx.z ? C1 : C0;

    const int tid = threadIdx.x;
    const int bn = blockIdx.x * 128;
    const int bm = blockIdx.y * 128;
    const int tx = tid & 15, ty = tid >> 4;

    const int rowA0 = tid >> 2;
    const int rowA1 = rowA0 + 64;
    const int qa = tid & 3;
    int m0 = bm + rowA0, m1 = bm + rowA1;
    const float* Xr0 = X + (size_t)(m0 & 31) * strideB + (size_t)(m0 >> 5) * strideS + qa * 4;
    const float* Xr1 = X + (size_t)(m1 & 31) * strideB + (size_t)(m1 >> 5) * strideS + qa * 4;
    const int krB = tid >> 5;
    const int nqB = tid & 31;
    const float* Wp0 = Wt + (size_t)krB * G3 + bn + nqB * 4;
    const float* Wp1 = Wt + (size_t)(krB + 8) * G3 + bn + nqB * 4;

    float2 acc[8][4];
#pragma unroll
    for (int i = 0; i < 8; i++)
#pragma unroll
        for (int j = 0; j < 4; j++) acc[i][j] = make_float2(0.f, 0.f);

    float4 ra0 = *(const float4*)(Xr0);
    float4 ra1 = *(const float4*)(Xr1);
    float4 rb0 = *(const float4*)(Wp0);
    float4 rb1 = *(const float4*)(Wp1);
    As[0][qa * 4 + 0][rowA0] = ra0.x;
    As[0][qa * 4 + 1][rowA0] = ra0.y;
    As[0][qa * 4 + 2][rowA0] = ra0.z;
    As[0][qa * 4 + 3][rowA0] = ra0.w;
    As[0][qa * 4 + 0][rowA1] = ra1.x;
    As[0][qa * 4 + 1][rowA1] = ra1.y;
    As[0][qa * 4 + 2][rowA1] = ra1.z;
    As[0][qa * 4 + 3][rowA1] = ra1.w;
    *(float4*)&Bs[0][krB][nqB * 4] = rb0;
    *(float4*)&Bs[0][krB + 8][nqB * 4] = rb1;
    __syncthreads();

    int buf = 0;
    for (int k0 = 0; k0 < K; k0 += 16) {
        const bool more = (k0 + 16 < K);
        if (more) {
            ra0 = *(const float4*)(Xr0 + k0 + 16);
            ra1 = *(const float4*)(Xr1 + k0 + 16);
            rb0 = *(const float4*)(Wp0 + (size_t)(k0 + 16) * G3);
            rb1 = *(const float4*)(Wp1 + (size_t)(k0 + 16) * G3);
        }
#pragma unroll
        for (int kk = 0; kk < 16; kk++) {
            float4 av0 = *(const float4*)&As[buf][kk][ty * 8];
            float4 av1 = *(const float4*)&As[buf][kk][ty * 8 + 4];
            float4 bv0 = *(const float4*)&Bs[buf][kk][tx * 4];
            float4 bv1 = *(const float4*)&Bs[buf][kk][tx * 4 + 64];
            float aa[8] = {av0.x, av0.y, av0.z, av0.w, av1.x, av1.y, av1.z, av1.w};
            float2 bb[4] = {make_float2(bv0.x, bv0.y), make_float2(bv0.z, bv0.w),
                            make_float2(bv1.x, bv1.y), make_float2(bv1.z, bv1.w)};
#pragma unroll
            for (int i = 0; i < 8; i++) {
                float2 a2 = make_float2(aa[i], aa[i]);
#pragma unroll
                for (int j = 0; j < 4; j++) acc[i][j] = ffma2(a2, bb[j], acc[i][j]);
            }
        }
        if (more) {
            int nb = buf ^ 1;
            As[nb][qa * 4 + 0][rowA0] = ra0.x;
            As[nb][qa * 4 + 1][rowA0] = ra0.y;
            As[nb][qa * 4 + 2][rowA0] = ra0.z;
            As[nb][qa * 4 + 3][rowA0] = ra0.w;
            As[nb][qa * 4 + 0][rowA1] = ra1.x;
            As[nb][qa * 4 + 1][rowA1] = ra1.y;
            As[nb][qa * 4 + 2][rowA1] = ra1.z;
            As[nb][qa * 4 + 3][rowA1] = ra1.w;
            *(float4*)&Bs[nb][krB][nqB * 4] = rb0;
            *(float4*)&Bs[nb][krB + 8][nqB * 4] = rb1;
            __syncthreads();
            buf = nb;
        }
    }

    float4 bsv0 = *(const float4*)(bias + bn + tx * 4);
    float4 bsv1 = *(const float4*)(bias + bn + 64 + tx * 4);
    float bv[8] = {bsv0.x, bsv0.y, bsv0.z, bsv0.w, bsv1.x, bsv1.y, bsv1.z, bsv1.w};
#pragma unroll
    for (int i = 0; i < 8; i++) {
        int m2 = bm + ty * 8 + i;
        float* crow = C + (size_t)m2 * G3 + bn;
        float4 v0 = make_float4(acc[i][0].x + bv[0], acc[i][0].y + bv[1],
                                acc[i][1].x + bv[2], acc[i][1].y + bv[3]);
        float4 v1 = make_float4(acc[i][2].x + bv[4], acc[i][2].y + bv[5],
                                acc[i][3].x + bv[6], acc[i][3].y + bv[7]);
        *(float4*)(crow + tx * 4) = v0;
        *(float4*)(crow + 64 + tx * 4) = v1;
    }
}

// ---------------- persistent recurrent layer (cp.async staged h) ----------------
__global__ __launch_bounds__(512, 1) void gru_layer(
    int layer, const float* __restrict__ bhh_f, const float* __restrict__ bhh_b)
{
    extern __shared__ float smem[];
    float* wsm  = smem;
    float2* red = (float2*)(smem + W_SM_FLOATS);   // overlays h staging (disjoint in time)

    const int dir  = blockIdx.y;
    const int jblk = blockIdx.x;
    const int tid  = threadIdx.x;
    const int kg   = tid >> 6;
    const int t64  = tid & 63;
    const int bg   = t64 >> 3;
    const int jp   = t64 & 7;
    const int j0   = jblk * 16 + jp * 2;
    const int b0   = bg * 4;

    const float* wsrc = g_whh_p[layer][dir] + (size_t)jblk * W_SM_FLOATS;
    for (int i = tid; i < W_SM_FLOATS / 4; i += 512)
        ((float4*)wsm)[i] = ((const float4*)wsrc)[i];

    const float* bhh = dir ? bhh_b : bhh_f;
    const float2 br  = *(const float2*)(bhh + j0);
    const float2 bz  = *(const float2*)(bhh + HH + j0);
    const float2 bn2 = *(const float2*)(bhh + 2 * HH + j0);
    const float* gx_base = g_gx[dir];

    float* hst_grp = smem + W_SM_FLOATS + kg * 1024;
    const unsigned hstg = (unsigned)__cvta_generic_to_shared(hst_grp);
    __syncthreads();

    for (int t = 0; t < SS; t++) {
        const float* hprev = g_h[dir][t & 1];
        const int s_sel = dir ? (SS - 1 - t) : t;
        const float* hsrc = hprev + kg * 128 * BB;

        // prologue: stage chunks 0, 1
#pragma unroll
        for (int pc = 0; pc < 2; pc++) {
            unsigned dst = hstg + pc * 2048 + t64 * 16;
            const float* src = hsrc + pc * 512 + t64 * 4;
            cpasync16(dst, src);
            cpasync16(dst + 1024, src + 256);
            asm volatile("cp.async.commit_group;" ::: "memory");
        }

        float2 xr[4], xz[4], xn[4];
        float4 hpa, hpb;
        if (kg == 0) {
#pragma unroll
            for (int bi = 0; bi < 4; bi++) {
                const float* gxp = gx_base + ((size_t)s_sel * BB + b0 + bi) * G3 + j0;
                xr[bi] = ldcg2(gxp);
                xz[bi] = ldcg2(gxp + HH);
                xn[bi] = ldcg2(gxp + 2 * HH);
            }
            hpa = ldcg4(hprev + j0 * BB + b0);
            hpb = ldcg4(hprev + (j0 + 1) * BB + b0);
        }

        float2 ar[4], az[4], an[4];
#pragma unroll
        for (int bi = 0; bi < 4; bi++) {
            ar[bi] = make_float2(0.f, 0.f);
            az[bi] = make_float2(0.f, 0.f);
            an[bi] = make_float2(0.f, 0.f);
        }

#pragma unroll
        for (int c = 0; c < 8; c++) {
            if (c < 7) asm volatile("cp.async.wait_group 1;" ::: "memory");
            else       asm volatile("cp.async.wait_group 0;" ::: "memory");
            __syncthreads();
            const float* hst = hst_grp + (c & 1) * 512;
            const float* wq  = wsm + (size_t)(kg * 128 + c * 16) * 48 + jp * 2;
#pragma unroll 4
            for (int kl = 0; kl < 16; kl++) {
                float4 h4 = *(const float4*)&hst[kl * 32 + b0];
                const float* w = wq + kl * 48;
                float2 wr = *(const float2*)(w);
                float2 wz = *(const float2*)(w + 16);
                float2 wn = *(const float2*)(w + 32);
                ar[0] = ffma2(bcast2(h4.x), wr, ar[0]);
                az[0] = ffma2(bcast2(h4.x), wz, az[0]);
                an[0] = ffma2(bcast2(h4.x), wn, an[0]);
                ar[1] = ffma2(bcast2(h4.y), wr, ar[1]);
                az[1] = ffma2(bcast2(h4.y), wz, az[1]);
                an[1] = ffma2(bcast2(h4.y), wn, an[1]);
                ar[2] = ffma2(bcast2(h4.z), wr, ar[2]);
                az[2] = ffma2(bcast2(h4.z), wz, az[2]);
                an[2] = ffma2(bcast2(h4.z), wn, an[2]);
                ar[3] = ffma2(bcast2(h4.w), wr, ar[3]);
                az[3] = ffma2(bcast2(h4.w), wz, az[3]);
                an[3] = ffma2(bcast2(h4.w), wn, an[3]);
            }
            __syncthreads();
            if (c + 2 < 8) {
                unsigned dst = hstg + (c & 1) * 2048 + t64 * 16;
                const float* src = hsrc + (c + 2) * 512 + t64 * 4;
                cpasync16(dst, src);
                cpasync16(dst + 1024, src + 256);
                asm volatile("cp.async.commit_group;" ::: "memory");
            }
        }

        // k-split reduction 8->4->2->1
        __syncthreads();
        if (kg >= 4) {
            int base = (kg - 4) * 768;
#pragma unroll
            for (int bi = 0; bi < 4; bi++) {
                red[base + (bi * 3 + 0) * 64 + t64] = ar[bi];
                red[base + (bi * 3 + 1) * 64 + t64] = az[bi];
                red[base + (bi * 3 + 2) * 64 + t64] = an[bi];
            }
        }
        __syncthreads();
        if (kg < 4) {
            int base = kg * 768;
#pragma unroll
            for (int bi = 0; bi < 4; bi++) {
                float2 vr = red[base + (bi * 3 + 0) * 64 + t64];
                float2 vz = red[base + (bi * 3 + 1) * 64 + t64];
                float2 vn = red[base + (bi * 3 + 2) * 64 + t64];
                ar[bi].x += vr.x; ar[bi].y += vr.y;
                az[bi].x += vz.x; az[bi].y += vz.y;
                an[bi].x += vn.x; an[bi].y += vn.y;
            }
        }
        __syncthreads();
        if (kg == 2 || kg == 3) {
            int base = (kg - 2) * 768;
#pragma unroll
            for (int bi = 0; bi < 4; bi++) {
                red[base + (bi * 3 + 0) * 64 + t64] = ar[bi];
                red[base + (bi * 3 + 1) * 64 + t64] = az[bi];
                red[base + (bi * 3 + 2) * 64 + t64] = an[bi];
            }
        }
        __syncthreads();
        if (kg < 2) {
            int base = kg * 768;
#pragma unroll
            for (int bi = 0; bi < 4; bi++) {
                float2 vr = red[base + (bi * 3 + 0) * 64 + t64];
                float2 vz = red[base + (bi * 3 + 1) * 64 + t64];
                float2 vn = red[base + (bi * 3 + 2) * 64 + t64];
                ar[bi].x += vr.x; ar[bi].y += vr.y;
                az[bi].x += vz.x; az[bi].y += vz.y;
                an[bi].x += vn.x; an[bi].y += vn.y;
            }
        }
        __syncthreads();
        if (kg == 1) {
#pragma unroll
            for (int bi = 0; bi < 4; bi++) {
                red[(bi * 3 + 0) * 64 + t64] = ar[bi];
                red[(bi * 3 + 1) * 64 + t64] = az[bi];
                red[(bi * 3 + 2) * 64 + t64] = an[bi];
            }
        }
        __syncthreads();
        if (kg == 0) {
            float h0n[4], h1n[4];
#pragma unroll
            for (int bi = 0; bi < 4; bi++) {
                float2 vr = red[(bi * 3 + 0) * 64 + t64];
                float2 vz = red[(bi * 3 + 1) * 64 + t64];
                float2 vn = red[(bi * 3 + 2) * 64 + t64];
                float sr0 = xr[bi].x + ar[bi].x + vr.x + br.x;
                float sr1 = xr[bi].y + ar[bi].y + vr.y + br.y;
                float sz0 = xz[bi].x + az[bi].x + vz.x + bz.x;
                float sz1 = xz[bi].y + az[bi].y + vz.y + bz.y;
                float sn0 = an[bi].x + vn.x + bn2.x;
                float sn1 = an[bi].y + vn.y + bn2.y;
                float r0 = sigmoidf_(sr0), r1 = sigmoidf_(sr1);
                float z0 = sigmoidf_(sz0), z1 = sigmoidf_(sz1);
                float n0 = tanh_fast(xn[bi].x + r0 * sn0);
                float n1 = tanh_fast(xn[bi].y + r1 * sn1);
                float hp0 = (bi == 0) ? hpa.x : (bi == 1) ? hpa.y : (bi == 2) ? hpa.z : hpa.w;
                float hp1 = (bi == 0) ? hpb.x : (bi == 1) ? hpb.y : (bi == 2) ? hpb.z : hpb.w;
                h0n[bi] = (1.f - z0) * n0 + z0 * hp0;
                h1n[bi] = (1.f - z1) * n1 + z1 * hp1;
            }
            float* hout = g_h[dir][(t + 1) & 1];
            *(float4*)(hout + j0 * BB + b0) = make_float4(h0n[0], h0n[1], h0n[2], h0n[3]);
            *(float4*)(hout + (j0 + 1) * BB + b0) = make_float4(h1n[0], h1n[1], h1n[2], h1n[3]);
            if (layer == 0) {
#pragma unroll
                for (int bi = 0; bi < 4; bi++)
                    *(float2*)(&g_out0[((size_t)(b0 + bi) * SS + s_sel) * H2 + dir * HH + j0]) =
                        make_float2(h0n[bi], h1n[bi]);
            }
        }

        dir_barrier(dir, (unsigned)(t + 1));
    }
}

// ---------------- zero hidden + barrier state (between layers) ----------------
__global__ void zero_h_k() {
    int i = blockIdx.x * blockDim.x + threadIdx.x;
    if (i < HH * BB) { g_h[0][0][i] = 0.f; g_h[1][0][i] = 0.f; }
    if (i < 2) g_bar_count[i] = 0u;
}

// ---------------- final output ----------------
__global__ void finalize_k(float* __restrict__ out) {
    int i = blockIdx.x * blockDim.x + threadIdx.x;
    if (i < BB * H2) {
        int b = i >> 11, c = i & 2047;
        out[i] = (c < HH) ? g_h[0][0][c * BB + b] : g_h[1][0][(c - HH) * BB + b];
    }
}

// ---------------- host ----------------
extern "C" void kernel_launch(void* const* d_in, const int* in_sizes, int n_in,
                              void* d_out, int out_size)
{
    const float* x       = (const float*)d_in[0];
    const float* w_ih_f0 = (const float*)d_in[1];
    const float* w_hh_f0 = (const float*)d_in[2];
    const float* b_ih_f0 = (const float*)d_in[3];
    const float* b_hh_f0 = (const float*)d_in[4];
    const float* w_ih_b0 = (const float*)d_in[5];
    const float* w_hh_b0 = (const float*)d_in[6];
    const float* b_ih_b0 = (const float*)d_in[7];
    const float* b_hh_b0 = (const float*)d_in[8];
    const float* w_ih_f1 = (const float*)d_in[9];
    const float* w_hh_f1 = (const float*)d_in[10];
    const float* b_ih_f1 = (const float*)d_in[11];
    const float* b_hh_f1 = (const float*)d_in[12];
    const float* w_ih_b1 = (const float*)d_in[13];
    const float* w_hh_b1 = (const float*)d_in[14];
    const float* b_ih_b1 = (const float*)d_in[15];
    const float* b_hh_b1 = (const float*)d_in[16];
    float* out = (float*)d_out;

    cudaFuncSetAttribute(gru_layer, cudaFuncAttributeMaxDynamicSharedMemorySize,
                         GRU_SMEM_BYTES);

    float *wih0, *wih1, *gx, *out0;
    cudaGetSymbolAddress((void**)&wih0, g_wih0_t);
    cudaGetSymbolAddress((void**)&wih1, g_wih1_t);
    cudaGetSymbolAddress((void**)&gx,   g_gx);
    cudaGetSymbolAddress((void**)&out0, g_out0);

    float* wih0_f = wih0;
    float* wih0_b = wih0 + (size_t)II * G3;
    float* wih1_f = wih1;
    float* wih1_b = wih1 + (size_t)H2 * G3;
    float* gx_f = gx;
    float* gx_b = gx + (size_t)BB * SS * G3;

    dim3 ggrid(G3 / 128, (BB * SS) / 128, 2);

    transpose_ih<<<dim3(96, 64, 4), dim3(32, 8)>>>(
        w_ih_f0, w_ih_b0, w_ih_f1, w_ih_b1, wih0_f, wih0_b, wih1_f, wih1_b);
    prepack_whh<<<dim3(12288, 4), 256>>>(w_hh_f0, w_hh_b0, w_hh_f1, w_hh_b1);
    gemm_gx2<<<ggrid, 256>>>(x, SS * II, II, II, wih0_f, wih0_b,
                             b_ih_f0, b_ih_b0, gx_f, gx_b);
    gru_layer<<<dim3(64, 2), 512, GRU_SMEM_BYTES>>>(0, b_hh_f0, b_hh_b0);

    gemm_gx2<<<ggrid, 256>>>(out0, SS * H2, H2, H2, wih1_f, wih1_b,
                             b_ih_f1, b_ih_b1, gx_f, gx_b);
    zero_h_k<<<(HH * BB + 255) / 256, 256>>>();
    gru_layer<<<dim3(64, 2), 512, GRU_SMEM_BYTES>>>(1, b_hh_f1, b_hh_b1);

    finalize_k<<<(BB * H2 + 255) / 256, 256>>>(out);
}

// round 15
// speedup vs baseline: 1.5101x; 1.2203x over previous
#include <cuda_runtime.h>
#include <cuda_bf16.h>
#include <math.h>

#define BB 32
#define SS 512
#define II 512
#define HH 1024
#define G3 3072
#define H2 2048
#define MTOT (BB * SS)

#define W_SM_FLOATS (1024 * 48)
#define HSTAGE_FLOATS (8 * 2 * 512)
#define GRU_SMEM_BYTES ((W_SM_FLOATS + HSTAGE_FLOATS) * 4)

#define KC 64
#define RSTRIDE 144
#define TILE_BYTES (384 * RSTRIDE)
#define GEMM_SMEM_BYTES (2 * TILE_BYTES)

#define WOFF_F0 0
#define WOFF_B0 (3072 * 512)
#define WOFF_F1 (2 * 3072 * 512)
#define WOFF_B1 (2 * 3072 * 512 + 3072 * 2048)
#define WTOT (2 * 3072 * 512 + 2 * 3072 * 2048)

__device__ float g_whh_p[2][2][HH * G3];
__device__ float g_gx[2][(size_t)MTOT * G3];
__device__ float g_h[2][2][HH * BB];
__device__ float g_out0[(size_t)MTOT * H2];
__device__ unsigned g_bar_count[2];
__device__ __align__(256) __nv_bfloat16 g_ahi[(size_t)MTOT * H2];
__device__ __align__(256) __nv_bfloat16 g_alo[(size_t)MTOT * H2];
__device__ __align__(256) __nv_bfloat16 g_whi[WTOT];
__device__ __align__(256) __nv_bfloat16 g_wlo[WTOT];

__device__ __forceinline__ float2 ffma2(float2 a, float2 b, float2 c) {
    unsigned long long A = *reinterpret_cast<unsigned long long*>(&a);
    unsigned long long B = *reinterpret_cast<unsigned long long*>(&b);
    unsigned long long C = *reinterpret_cast<unsigned long long*>(&c);
    unsigned long long D;
    asm("fma.rn.f32x2 %0, %1, %2, %3;" : "=l"(D) : "l"(A), "l"(B), "l"(C));
    return *reinterpret_cast<float2*>(&D);
}
__device__ __forceinline__ float2 bcast2(float x) { return make_float2(x, x); }
__device__ __forceinline__ float tanh_fast(float x) {
    float y;
    asm("tanh.approx.f32 %0, %1;" : "=f"(y) : "f"(x));
    return y;
}
__device__ __forceinline__ float sigmoidf_(float x) {
    return fmaf(0.5f, tanh_fast(0.5f * x), 0.5f);
}
__device__ __forceinline__ float4 ldcg4(const float* p) {
    float4 v;
    asm volatile("ld.global.cg.v4.f32 {%0,%1,%2,%3}, [%4];"
                 : "=f"(v.x), "=f"(v.y), "=f"(v.z), "=f"(v.w) : "l"(p));
    return v;
}
__device__ __forceinline__ float2 ldcg2(const float* p) {
    float2 v;
    asm volatile("ld.global.cg.v2.f32 {%0,%1}, [%2];" : "=f"(v.x), "=f"(v.y) : "l"(p));
    return v;
}
__device__ __forceinline__ void cpasync16(unsigned dst, const void* src) {
    asm volatile("cp.async.cg.shared.global [%0], [%1], 16;" :: "r"(dst), "l"(src) : "memory");
}
__device__ __forceinline__ unsigned lds32(unsigned a) {
    unsigned v;
    asm volatile("ld.shared.b32 %0, [%1];" : "=r"(v) : "r"(a));
    return v;
}
__device__ __forceinline__ void mma_bf16(float* c, const unsigned* a, const unsigned* b) {
    asm volatile(
        "mma.sync.aligned.m16n8k16.row.col.f32.bf16.bf16.f32 "
        "{%0,%1,%2,%3}, {%4,%5,%6,%7}, {%8,%9}, {%0,%1,%2,%3};"
        : "+f"(c[0]), "+f"(c[1]), "+f"(c[2]), "+f"(c[3])
        : "r"(a[0]), "r"(a[1]), "r"(a[2]), "r"(a[3]), "r"(b[0]), "r"(b[1]));
}

__device__ __forceinline__ void dir_barrier(int dir, unsigned n) {
    __syncthreads();
    if (threadIdx.x == 0) {
        unsigned* cnt = &g_bar_count[dir];
        asm volatile("red.release.gpu.global.add.u32 [%0], 1;" :: "l"(cnt) : "memory");
        const unsigned target = n * 64u;
        unsigned cur;
        do {
            asm volatile("ld.acquire.gpu.global.u32 %0, [%1];"
                         : "=r"(cur) : "l"(cnt) : "memory");
            if (cur >= target) break;
            __nanosleep(16);
        } while (true);
    }
    __syncthreads();
}

__global__ void conv_x(const float* __restrict__ x) {
    size_t idx = (size_t)blockIdx.x * 256 + threadIdx.x;
    int m = (int)(idx >> 9);
    int k = (int)(idx & 511);
    int b = m & 31;
    int s = m >> 5;
    float v = x[((size_t)b * SS + s) * II + k];
    __nv_bfloat16 hi = __float2bfloat16_rn(v);
    g_ahi[idx] = hi;
    g_alo[idx] = __float2bfloat16_rn(v - __bfloat162float(hi));
}

__global__ void conv_h() {
    size_t idx = (size_t)blockIdx.x * 256 + threadIdx.x;
    int m = (int)(idx >> 11);
    int c = (int)(idx & 2047);
    int b = m & 31;
    int s = m >> 5;
    float v = g_out0[((size_t)b * SS + s) * H2 + c];
    __nv_bfloat16 hi = __float2bfloat16_rn(v);
    g_ahi[idx] = hi;
    g_alo[idx] = __float2bfloat16_rn(v - __bfloat162float(hi));
}

__global__ void conv_w(const float* w_f0, const float* w_b0,
                       const float* w_f1, const float* w_b1) {
    int mat = blockIdx.y;
    size_t sz  = (mat < 2) ? (size_t)3072 * 512 : (size_t)3072 * 2048;
    size_t off = (mat == 0) ? WOFF_F0 : (mat == 1) ? WOFF_B0 : (mat == 2) ? WOFF_F1 : WOFF_B1;
    const float* src = (mat == 0) ? w_f0 : (mat == 1) ? w_b0 : (mat == 2) ? w_f1 : w_b1;
    size_t idx = (size_t)blockIdx.x * 256 + threadIdx.x;
    if (idx >= sz) return;
    float v = src[idx];
    __nv_bfloat16 hi = __float2bfloat16_rn(v);
    g_whi[off + idx] = hi;
    g_wlo[off + idx] = __float2bfloat16_rn(v - __bfloat162float(hi));
}

__global__ void prepack_whh(const float* w00, const float* w01,
                            const float* w10, const float* w11) {
    int mat = blockIdx.y;
    const float* src = (mat == 0) ? w00 : (mat == 1) ? w01 : (mat == 2) ? w10 : w11;
    float* dst = g_whh_p[mat >> 1][mat & 1];
    int idx = blockIdx.x * 256 + threadIdx.x;
    int k = idx & 1023;
    int n = idx >> 10;
    int g = n >> 10;
    int nj = n & 1023;
    int jblk = nj >> 4;
    int jp = (nj >> 1) & 7;
    int c  = nj & 1;
    dst[jblk * W_SM_FLOATS + k * 48 + g * 16 + jp * 2 + c] = src[idx];
    if (mat == 0) {
        if (idx < HH * BB) { g_h[0][0][idx] = 0.f; g_h[1][0][idx] = 0.f; }
        if (idx < 2) g_bar_count[idx] = 0u;
    }
}

__device__ __forceinline__ void copy_tile(
    unsigned dstbase, int tid, int kpos, int kdim, int mbase, int nbase,
    const __nv_bfloat16* wh, const __nv_bfloat16* wl)
{
#pragma unroll
    for (int j = 0; j < 12; j++) {
        int seg = tid + 256 * j;
        int rr = seg >> 3;
        int oo = seg & 7;
        unsigned d = dstbase + (unsigned)rr * RSTRIDE + (unsigned)oo * 16;
        const __nv_bfloat16* s;
        if (rr < 128) {
            s = g_ahi + (size_t)(mbase + rr) * kdim + kpos + oo * 8;
        } else if (rr < 256) {
            s = g_alo + (size_t)(mbase + rr - 128) * kdim + kpos + oo * 8;
        } else if (rr < 320) {
            s = wh + (size_t)(nbase + rr - 256) * kdim + kpos + oo * 8;
        } else {
            s = wl + (size_t)(nbase + rr - 320) * kdim + kpos + oo * 8;
        }
        cpasync16(d, s);
    }
    asm volatile("cp.async.commit_group;" ::: "memory");
}

__global__ __launch_bounds__(256, 2) void gemm_hmma(
    const __nv_bfloat16* __restrict__ wh0, const __nv_bfloat16* __restrict__ wl0,
    const __nv_bfloat16* __restrict__ wh1, const __nv_bfloat16* __restrict__ wl1,
    const float* __restrict__ bias0, const float* __restrict__ bias1, int kdim)
{
    extern __shared__ char smem[];
    const unsigned qsb = (unsigned)__cvta_generic_to_shared(smem);
    const int tid = threadIdx.x;
    const int nbase = blockIdx.x * 64;
    const int mbase = blockIdx.y * 128;
    const int dir = blockIdx.z;
    const __nv_bfloat16* wh = dir ? wh1 : wh0;
    const __nv_bfloat16* wl = dir ? wl1 : wl0;
    const float* bias = dir ? bias1 : bias0;
    float* cptr = g_gx[dir];

    const int wid = tid >> 5;
    const int lane = tid & 31;
    const int qgid = lane >> 2;
    const int qt4 = lane & 3;
    const int qmw = (wid & 1) * 64;
    const int qnw = (wid >> 1) * 16;
    const int nchunk = kdim >> 6;

    float acc[32];
    unsigned fa[16];
    unsigned fg[16];
    unsigned pb[4];
    unsigned qb[4];
#pragma unroll
    for (int i = 0; i < 32; i++) acc[i] = 0.0f;

    copy_tile(qsb, tid, 0, kdim, mbase, nbase, wh, wl);
    copy_tile(qsb + TILE_BYTES, tid, KC, kdim, mbase, nbase, wh, wl);

    for (int c = 0; c < nchunk; c++) {
        if (c + 1 < nchunk) {
            asm volatile("cp.async.wait_group 1;" ::: "memory");
        } else {
            asm volatile("cp.async.wait_group 0;" ::: "memory");
        }
        __syncthreads();
        unsigned qtb = qsb + (unsigned)(c & 1) * TILE_BYTES;
#pragma unroll
        for (int kk = 0; kk < KC; kk += 16) {
            unsigned kbyte = (unsigned)(kk + qt4 * 2) * 2u;
#pragma unroll
            for (int mb = 0; mb < 4; mb++) {
                unsigned aa0 = qtb + (unsigned)(qmw + mb * 16 + qgid) * RSTRIDE + kbyte;
                fa[mb * 4 + 0] = lds32(aa0);
                fa[mb * 4 + 1] = lds32(aa0 + 8 * RSTRIDE);
                fa[mb * 4 + 2] = lds32(aa0 + 16);
                fa[mb * 4 + 3] = lds32(aa0 + 8 * RSTRIDE + 16);
                fg[mb * 4 + 0] = lds32(aa0 + 128 * RSTRIDE);
                fg[mb * 4 + 1] = lds32(aa0 + 136 * RSTRIDE);
                fg[mb * 4 + 2] = lds32(aa0 + 128 * RSTRIDE + 16);
                fg[mb * 4 + 3] = lds32(aa0 + 136 * RSTRIDE + 16);
            }
#pragma unroll
            for (int nb = 0; nb < 2; nb++) {
                unsigned bb0 = qtb + (unsigned)(256 + qnw + nb * 8 + qgid) * RSTRIDE + kbyte;
                pb[nb * 2 + 0] = lds32(bb0);
                pb[nb * 2 + 1] = lds32(bb0 + 16);
                qb[nb * 2 + 0] = lds32(bb0 + 64 * RSTRIDE);
                qb[nb * 2 + 1] = lds32(bb0 + 64 * RSTRIDE + 16);
            }
#pragma unroll
            for (int mb = 0; mb < 4; mb++) {
#pragma unroll
                for (int nb = 0; nb < 2; nb++) {
                    mma_bf16(acc + (mb * 2 + nb) * 4, fa + mb * 4, pb + nb * 2);
                    mma_bf16(acc + (mb * 2 + nb) * 4, fg + mb * 4, pb + nb * 2);
                    mma_bf16(acc + (mb * 2 + nb) * 4, fa + mb * 4, qb + nb * 2);
                }
            }
        }
        __syncthreads();
        if (c + 2 < nchunk) {
            copy_tile(qsb + (unsigned)(c & 1) * TILE_BYTES, tid, (c + 2) * KC,
                      kdim, mbase, nbase, wh, wl);
        }
    }

#pragma unroll
    for (int nb = 0; nb < 2; nb++) {
        int n0 = nbase + qnw + nb * 8 + qt4 * 2;
        float bvx = bias[n0];
        float bvy = bias[n0 + 1];
#pragma unroll
        for (int mb = 0; mb < 4; mb++) {
            int m0 = mbase + qmw + mb * 16 + qgid;
            float* cr = acc + (mb * 2 + nb) * 4;
            float2 u0 = make_float2(cr[0] + bvx, cr[1] + bvy);
            float2 u1 = make_float2(cr[2] + bvx, cr[3] + bvy);
            *(float2*)(cptr + (size_t)m0 * G3 + n0) = u0;
            *(float2*)(cptr + (size_t)(m0 + 8) * G3 + n0) = u1;
        }
    }
}

__global__ __launch_bounds__(512, 1) void gru_layer(
    int layer, const float* __restrict__ bhh_f, const float* __restrict__ bhh_b)
{
    extern __shared__ float smemf[];
    float* wsm  = smemf;
    float2* red = (float2*)(smemf + W_SM_FLOATS);

    const int dir  = blockIdx.y;
    const int jblk = blockIdx.x;
    const int tid  = threadIdx.x;
    const int kg   = tid >> 6;
    const int t64  = tid & 63;
    const int bg   = t64 >> 3;
    const int jp   = t64 & 7;
    const int j0   = jblk * 16 + jp * 2;
    const int b0   = bg * 4;

    const float* wsrc = g_whh_p[layer][dir] + (size_t)jblk * W_SM_FLOATS;
    for (int i = tid; i < W_SM_FLOATS / 4; i += 512)
        ((float4*)wsm)[i] = ((const float4*)wsrc)[i];

    const float* bhh = dir ? bhh_b : bhh_f;
    const float2 br  = *(const float2*)(bhh + j0);
    const float2 bz  = *(const float2*)(bhh + HH + j0);
    const float2 bn2 = *(const float2*)(bhh + 2 * HH + j0);
    const float* gx_base = g_gx[dir];

    float* hst_grp = smemf + W_SM_FLOATS + kg * 1024;
    const unsigned hstg = (unsigned)__cvta_generic_to_shared(hst_grp);
    __syncthreads();

    for (int t = 0; t < SS; t++) {
        const float* hprev = g_h[dir][t & 1];
        const int s_sel = dir ? (SS - 1 - t) : t;
        const float* hsrc = hprev + kg * 128 * BB;

#pragma unroll
        for (int pc = 0; pc < 2; pc++) {
            unsigned dst = hstg + pc * 2048 + t64 * 16;
            const float* src = hsrc + pc * 512 + t64 * 4;
            cpasync16(dst, src);
            cpasync16(dst + 1024, src + 256);
            asm volatile("cp.async.commit_group;" ::: "memory");
        }

        float2 xr[4], xz[4], xn[4];
        float4 hpa, hpb;
        if (kg == 0) {
#pragma unroll
            for (int bi = 0; bi < 4; bi++) {
                const float* gxp = gx_base + ((size_t)s_sel * BB + b0 + bi) * G3 + j0;
                xr[bi] = ldcg2(gxp);
                xz[bi] = ldcg2(gxp + HH);
                xn[bi] = ldcg2(gxp + 2 * HH);
            }
            hpa = ldcg4(hprev + j0 * BB + b0);
            hpb = ldcg4(hprev + (j0 + 1) * BB + b0);
        }

        float2 ar[4], az[4], an[4];
#pragma unroll
        for (int bi = 0; bi < 4; bi++) {
            ar[bi] = make_float2(0.f, 0.f);
            az[bi] = make_float2(0.f, 0.f);
            an[bi] = make_float2(0.f, 0.f);
        }

#pragma unroll
        for (int c = 0; c < 8; c++) {
            if (c < 7) asm volatile("cp.async.wait_group 1;" ::: "memory");
            else       asm volatile("cp.async.wait_group 0;" ::: "memory");
            __syncthreads();
            const float* hst = hst_grp + (c & 1) * 512;
            const float* wq  = wsm + (size_t)(kg * 128 + c * 16) * 48 + jp * 2;
#pragma unroll 4
            for (int kl = 0; kl < 16; kl++) {
                float4 h4 = *(const float4*)&hst[kl * 32 + b0];
                const float* w = wq + kl * 48;
                float2 wr = *(const float2*)(w);
                float2 wz = *(const float2*)(w + 16);
                float2 wn = *(const float2*)(w + 32);
                ar[0] = ffma2(bcast2(h4.x), wr, ar[0]);
                az[0] = ffma2(bcast2(h4.x), wz, az[0]);
                an[0] = ffma2(bcast2(h4.x), wn, an[0]);
                ar[1] = ffma2(bcast2(h4.y), wr, ar[1]);
                az[1] = ffma2(bcast2(h4.y), wz, az[1]);
                an[1] = ffma2(bcast2(h4.y), wn, an[1]);
                ar[2] = ffma2(bcast2(h4.z), wr, ar[2]);
                az[2] = ffma2(bcast2(h4.z), wz, az[2]);
                an[2] = ffma2(bcast2(h4.z), wn, an[2]);
                ar[3] = ffma2(bcast2(h4.w), wr, ar[3]);
                az[3] = ffma2(bcast2(h4.w), wz, az[3]);
                an[3] = ffma2(bcast2(h4.w), wn, an[3]);
            }
            __syncthreads();
            if (c + 2 < 8) {
                unsigned dst = hstg + (c & 1) * 2048 + t64 * 16;
                const float* src = hsrc + (c + 2) * 512 + t64 * 4;
                cpasync16(dst, src);
                cpasync16(dst + 1024, src + 256);
                asm volatile("cp.async.commit_group;" ::: "memory");
            }
        }

        __syncthreads();
        if (kg >= 4) {
            int rbase = (kg - 4) * 768;
#pragma unroll
            for (int bi = 0; bi < 4; bi++) {
                red[rbase + (bi * 3 + 0) * 64 + t64] = ar[bi];
                red[rbase + (bi * 3 + 1) * 64 + t64] = az[bi];
                red[rbase + (bi * 3 + 2) * 64 + t64] = an[bi];
            }
        }
        __syncthreads();
        if (kg < 4) {
            int rbase = kg * 768;
#pragma unroll
            for (int bi = 0; bi < 4; bi++) {
                float2 vr = red[rbase + (bi * 3 + 0) * 64 + t64];
                float2 vz = red[rbase + (bi * 3 + 1) * 64 + t64];
                float2 vn = red[rbase + (bi * 3 + 2) * 64 + t64];
                ar[bi].x += vr.x; ar[bi].y += vr.y;
                az[bi].x += vz.x; az[bi].y += vz.y;
                an[bi].x += vn.x; an[bi].y += vn.y;
            }
        }
        __syncthreads();
        if (kg == 2 || kg == 3) {
            int rbase = (kg - 2) * 768;
#pragma unroll
            for (int bi = 0; bi < 4; bi++) {
                red[rbase + (bi * 3 + 0) * 64 + t64] = ar[bi];
                red[rbase + (bi * 3 + 1) * 64 + t64] = az[bi];
                red[rbase + (bi * 3 + 2) * 64 + t64] = an[bi];
            }
        }
        __syncthreads();
        if (kg < 2) {
            int rbase = kg * 768;
#pragma unroll
            for (int bi = 0; bi < 4; bi++) {
                float2 vr = red[rbase + (bi * 3 + 0) * 64 + t64];
                float2 vz = red[rbase + (bi * 3 + 1) * 64 + t64];
                float2 vn = red[rbase + (bi * 3 + 2) * 64 + t64];
                ar[bi].x += vr.x; ar[bi].y += vr.y;
                az[bi].x += vz.x; az[bi].y += vz.y;
                an[bi].x += vn.x; an[bi].y += vn.y;
            }
        }
        __syncthreads();
        if (kg == 1) {
#pragma unroll
            for (int bi = 0; bi < 4; bi++) {
                red[(bi * 3 + 0) * 64 + t64] = ar[bi];
                red[(bi * 3 + 1) * 64 + t64] = az[bi];
                red[(bi * 3 + 2) * 64 + t64] = an[bi];
            }
        }
        __syncthreads();
        if (kg == 0) {
            float h0n[4], h1n[4];
#pragma unroll
            for (int bi = 0; bi < 4; bi++) {
                float2 vr = red[(bi * 3 + 0) * 64 + t64];
                float2 vz = red[(bi * 3 + 1) * 64 + t64];
                float2 vn = red[(bi * 3 + 2) * 64 + t64];
                float sr0 = xr[bi].x + ar[bi].x + vr.x + br.x;
                float sr1 = xr[bi].y + ar[bi].y + vr.y + br.y;
                float sz0 = xz[bi].x + az[bi].x + vz.x + bz.x;
                float sz1 = xz[bi].y + az[bi].y + vz.y + bz.y;
                float sn0 = an[bi].x + vn.x + bn2.x;
                float sn1 = an[bi].y + vn.y + bn2.y;
                float r0 = sigmoidf_(sr0), r1 = sigmoidf_(sr1);
                float z0 = sigmoidf_(sz0), z1 = sigmoidf_(sz1);
                float n0 = tanh_fast(xn[bi].x + r0 * sn0);
                float n1 = tanh_fast(xn[bi].y + r1 * sn1);
                float hp0 = (bi == 0) ? hpa.x : (bi == 1) ? hpa.y : (bi == 2) ? hpa.z : hpa.w;
                float hp1 = (bi == 0) ? hpb.x : (bi == 1) ? hpb.y : (bi == 2) ? hpb.z : hpb.w;
                h0n[bi] = (1.f - z0) * n0 + z0 * hp0;
                h1n[bi] = (1.f - z1) * n1 + z1 * hp1;
            }
            float* hout = g_h[dir][(t + 1) & 1];
            *(float4*)(hout + j0 * BB + b0) = make_float4(h0n[0], h0n[1], h0n[2], h0n[3]);
            *(float4*)(hout + (j0 + 1) * BB + b0) = make_float4(h1n[0], h1n[1], h1n[2], h1n[3]);
            if (layer == 0) {
#pragma unroll
                for (int bi = 0; bi < 4; bi++)
                    *(float2*)(&g_out0[((size_t)(b0 + bi) * SS + s_sel) * H2 + dir * HH + j0]) =
                        make_float2(h0n[bi], h1n[bi]);
            }
        }

        dir_barrier(dir, (unsigned)(t + 1));
    }
}

__global__ void zero_h_k() {
    int i = blockIdx.x * blockDim.x + threadIdx.x;
    if (i < HH * BB) { g_h[0][0][i] = 0.f; g_h[1][0][i] = 0.f; }
    if (i < 2) g_bar_count[i] = 0u;
}

__global__ void finalize_k(float* __restrict__ out) {
    int i = blockIdx.x * blockDim.x + threadIdx.x;
    if (i < BB * H2) {
        int b = i >> 11, c = i & 2047;
        out[i] = (c < HH) ? g_h[0][0][c * BB + b] : g_h[1][0][(c - HH) * BB + b];
    }
}

extern "C" void kernel_launch(void* const* d_in, const int* in_sizes, int n_in,
                              void* d_out, int out_size)
{
    const float* x       = (const float*)d_in[0];
    const float* w_ih_f0 = (const float*)d_in[1];
    const float* w_hh_f0 = (const float*)d_in[2];
    const float* b_ih_f0 = (const float*)d_in[3];
    const float* b_hh_f0 = (const float*)d_in[4];
    const float* w_ih_b0 = (const float*)d_in[5];
    const float* w_hh_b0 = (const float*)d_in[6];
    const float* b_ih_b0 = (const float*)d_in[7];
    const float* b_hh_b0 = (const float*)d_in[8];
    const float* w_ih_f1 = (const float*)d_in[9];
    const float* w_hh_f1 = (const float*)d_in[10];
    const float* b_ih_f1 = (const float*)d_in[11];
    const float* b_hh_f1 = (const float*)d_in[12];
    const float* w_ih_b1 = (const float*)d_in[13];
    const float* w_hh_b1 = (const float*)d_in[14];
    const float* b_ih_b1 = (const float*)d_in[15];
    const float* b_hh_b1 = (const float*)d_in[16];
    float* out = (float*)d_out;

    cudaFuncSetAttribute(gru_layer, cudaFuncAttributeMaxDynamicSharedMemorySize,
                         GRU_SMEM_BYTES);
    cudaFuncSetAttribute(gemm_hmma, cudaFuncAttributeMaxDynamicSharedMemorySize,
                         GEMM_SMEM_BYTES);

    void *whi_v, *wlo_v;
    cudaGetSymbolAddress(&whi_v, g_whi);
    cudaGetSymbolAddress(&wlo_v, g_wlo);
    __nv_bfloat16* whi = (__nv_bfloat16*)whi_v;
    __nv_bfloat16* wlo = (__nv_bfloat16*)wlo_v;

    dim3 ggrid(G3 / 64, MTOT / 128, 2);

    conv_x<<<(MTOT * II) / 256, 256>>>(x);
    conv_w<<<dim3(24576, 4), 256>>>(w_ih_f0, w_ih_b0, w_ih_f1, w_ih_b1);
    prepack_whh<<<dim3(12288, 4), 256>>>(w_hh_f0, w_hh_b0, w_hh_f1, w_hh_b1);
    gemm_hmma<<<ggrid, 256, GEMM_SMEM_BYTES>>>(
        whi + WOFF_F0, wlo + WOFF_F0, whi + WOFF_B0, wlo + WOFF_B0,
        b_ih_f0, b_ih_b0, 512);
    gru_layer<<<dim3(64, 2), 512, GRU_SMEM_BYTES>>>(0, b_hh_f0, b_hh_b0);
    conv_h<<<((size_t)MTOT * H2) / 256, 256>>>();
    gemm_hmma<<<ggrid, 256, GEMM_SMEM_BYTES>>>(
        whi + WOFF_F1, wlo + WOFF_F1, whi + WOFF_B1, wlo + WOFF_B1,
        b_ih_f1, b_ih_b1, 2048);
    zero_h_k<<<(HH * BB + 255) / 256, 256>>>();
    gru_layer<<<dim3(64, 2), 512, GRU_SMEM_BYTES>>>(1, b_hh_f1, b_hh_b1);

    finalize_k<<<(BB * H2 + 255) / 256, 256>>>(out);
}

// round 16
// speedup vs baseline: 1.5489x; 1.0257x over previous
#include <cuda_runtime.h>
#include <cuda_bf16.h>
#include <math.h>

#define BB 32
#define SS 512
#define II 512
#define HH 1024
#define G3 3072
#define H2 2048
#define MTOT (BB * SS)

#define W_SM_FLOATS (1024 * 48)
#define HSTAGE_FLOATS (8 * 2 * 512)
#define GRU_SMEM_BYTES ((W_SM_FLOATS + HSTAGE_FLOATS) * 4)

#define KC 64
#define RSTRIDE 144
#define TILE_BYTES (384 * RSTRIDE)
#define GEMM_SMEM_BYTES (2 * TILE_BYTES)

#define WOFF_F0 0
#define WOFF_B0 (3072 * 512)
#define WOFF_F1 (2 * 3072 * 512)
#define WOFF_B1 (2 * 3072 * 512 + 3072 * 2048)
#define WTOT (2 * 3072 * 512 + 2 * 3072 * 2048)

__device__ float g_whh_p[2][2][HH * G3];
__device__ float g_gx[2][(size_t)MTOT * G3];
__device__ float g_h[2][2][HH * BB];
__device__ unsigned g_bar_count[2];
__device__ __align__(256) __nv_bfloat16 g_ahi[(size_t)MTOT * H2];
__device__ __align__(256) __nv_bfloat16 g_alo[(size_t)MTOT * H2];
__device__ __align__(256) __nv_bfloat16 g_whi[WTOT];
__device__ __align__(256) __nv_bfloat16 g_wlo[WTOT];

__device__ __forceinline__ float2 ffma2(float2 a, float2 b, float2 c) {
    unsigned long long A = *reinterpret_cast<unsigned long long*>(&a);
    unsigned long long B = *reinterpret_cast<unsigned long long*>(&b);
    unsigned long long C = *reinterpret_cast<unsigned long long*>(&c);
    unsigned long long D;
    asm("fma.rn.f32x2 %0, %1, %2, %3;" : "=l"(D) : "l"(A), "l"(B), "l"(C));
    return *reinterpret_cast<float2*>(&D);
}
__device__ __forceinline__ float2 bcast2(float x) { return make_float2(x, x); }
__device__ __forceinline__ float tanh_fast(float x) {
    float y;
    asm("tanh.approx.f32 %0, %1;" : "=f"(y) : "f"(x));
    return y;
}
__device__ __forceinline__ float sigmoidf_(float x) {
    return fmaf(0.5f, tanh_fast(0.5f * x), 0.5f);
}
__device__ __forceinline__ float4 ldcg4(const float* p) {
    float4 v;
    asm volatile("ld.global.cg.v4.f32 {%0,%1,%2,%3}, [%4];"
                 : "=f"(v.x), "=f"(v.y), "=f"(v.z), "=f"(v.w) : "l"(p));
    return v;
}
__device__ __forceinline__ float2 ldcg2(const float* p) {
    float2 v;
    asm volatile("ld.global.cg.v2.f32 {%0,%1}, [%2];" : "=f"(v.x), "=f"(v.y) : "l"(p));
    return v;
}
__device__ __forceinline__ void cpasync16(unsigned dst, const void* src) {
    asm volatile("cp.async.cg.shared.global [%0], [%1], 16;" :: "r"(dst), "l"(src) : "memory");
}
__device__ __forceinline__ void ldmx4(unsigned* r, unsigned addr) {
    asm volatile("ldmatrix.sync.aligned.m8n8.x4.shared.b16 {%0,%1,%2,%3}, [%4];"
                 : "=r"(r[0]), "=r"(r[1]), "=r"(r[2]), "=r"(r[3]) : "r"(addr));
}
__device__ __forceinline__ void ldmx2(unsigned* r, unsigned addr) {
    asm volatile("ldmatrix.sync.aligned.m8n8.x2.shared.b16 {%0,%1}, [%2];"
                 : "=r"(r[0]), "=r"(r[1]) : "r"(addr));
}
__device__ __forceinline__ void mma_bf16(float* c, const unsigned* a, const unsigned* b) {
    asm volatile(
        "mma.sync.aligned.m16n8k16.row.col.f32.bf16.bf16.f32 "
        "{%0,%1,%2,%3}, {%4,%5,%6,%7}, {%8,%9}, {%0,%1,%2,%3};"
        : "+f"(c[0]), "+f"(c[1]), "+f"(c[2]), "+f"(c[3])
        : "r"(a[0]), "r"(a[1]), "r"(a[2]), "r"(a[3]), "r"(b[0]), "r"(b[1]));
}

__device__ __forceinline__ void dir_barrier(int dir, unsigned n) {
    __syncthreads();
    if (threadIdx.x == 0) {
        unsigned* cnt = &g_bar_count[dir];
        asm volatile("red.release.gpu.global.add.u32 [%0], 1;" :: "l"(cnt) : "memory");
        const unsigned target = n * 64u;
        unsigned cur;
        do {
            asm volatile("ld.acquire.gpu.global.u32 %0, [%1];"
                         : "=r"(cur) : "l"(cnt) : "memory");
            if (cur >= target) break;
            __nanosleep(16);
        } while (true);
    }
    __syncthreads();
}

__global__ void conv_x(const float* __restrict__ x) {
    size_t idx = (size_t)blockIdx.x * 256 + threadIdx.x;
    int m = (int)(idx >> 9);
    int k = (int)(idx & 511);
    int b = m & 31;
    int s = m >> 5;
    float v = x[((size_t)b * SS + s) * II + k];
    __nv_bfloat16 hi = __float2bfloat16_rn(v);
    g_ahi[idx] = hi;
    g_alo[idx] = __float2bfloat16_rn(v - __bfloat162float(hi));
}

__global__ void conv_w(const float* w_f0, const float* w_b0,
                       const float* w_f1, const float* w_b1) {
    int mat = blockIdx.y;
    size_t sz  = (mat < 2) ? (size_t)3072 * 512 : (size_t)3072 * 2048;
    size_t off = (mat == 0) ? WOFF_F0 : (mat == 1) ? WOFF_B0 : (mat == 2) ? WOFF_F1 : WOFF_B1;
    const float* src = (mat == 0) ? w_f0 : (mat == 1) ? w_b0 : (mat == 2) ? w_f1 : w_b1;
    size_t idx = (size_t)blockIdx.x * 256 + threadIdx.x;
    if (idx >= sz) return;
    float v = src[idx];
    __nv_bfloat16 hi = __float2bfloat16_rn(v);
    g_whi[off + idx] = hi;
    g_wlo[off + idx] = __float2bfloat16_rn(v - __bfloat162float(hi));
}

__global__ void prepack_whh(const float* w00, const float* w01,
                            const float* w10, const float* w11) {
    int mat = blockIdx.y;
    const float* src = (mat == 0) ? w00 : (mat == 1) ? w01 : (mat == 2) ? w10 : w11;
    float* dst = g_whh_p[mat >> 1][mat & 1];
    int idx = blockIdx.x * 256 + threadIdx.x;
    int k = idx & 1023;
    int n = idx >> 10;
    int g = n >> 10;
    int nj = n & 1023;
    int jblk = nj >> 4;
    int jp = (nj >> 1) & 7;
    int c  = nj & 1;
    dst[jblk * W_SM_FLOATS + k * 48 + g * 16 + jp * 2 + c] = src[idx];
    if (mat == 0) {
        if (idx < HH * BB) { g_h[0][0][idx] = 0.f; g_h[1][0][idx] = 0.f; }
        if (idx < 2) g_bar_count[idx] = 0u;
    }
}

__device__ __forceinline__ void copy_tile(
    unsigned dstbase, int tid, int kpos, int kdim, int mbase, int nbase,
    const __nv_bfloat16* wh, const __nv_bfloat16* wl)
{
#pragma unroll
    for (int j = 0; j < 12; j++) {
        int seg = tid + 256 * j;
        int rr = seg >> 3;
        int oo = seg & 7;
        unsigned d = dstbase + (unsigned)rr * RSTRIDE + (unsigned)oo * 16;
        const __nv_bfloat16* s;
        if (rr < 128) {
            s = g_ahi + (size_t)(mbase + rr) * kdim + kpos + oo * 8;
        } else if (rr < 256) {
            s = g_alo + (size_t)(mbase + rr - 128) * kdim + kpos + oo * 8;
        } else if (rr < 320) {
            s = wh + (size_t)(nbase + rr - 256) * kdim + kpos + oo * 8;
        } else {
            s = wl + (size_t)(nbase + rr - 320) * kdim + kpos + oo * 8;
        }
        cpasync16(d, s);
    }
    asm volatile("cp.async.commit_group;" ::: "memory");
}

__global__ __launch_bounds__(256, 2) void gemm_hmma(
    const __nv_bfloat16* __restrict__ wh0, const __nv_bfloat16* __restrict__ wl0,
    const __nv_bfloat16* __restrict__ wh1, const __nv_bfloat16* __restrict__ wl1,
    const float* __restrict__ bias0, const float* __restrict__ bias1, int kdim)
{
    extern __shared__ char smem[];
    const unsigned qsb = (unsigned)__cvta_generic_to_shared(smem);
    const int tid = threadIdx.x;
    const int nbase = blockIdx.x * 64;
    const int mbase = blockIdx.y * 128;
    const int dir = blockIdx.z;
    const __nv_bfloat16* wh = dir ? wh1 : wh0;
    const __nv_bfloat16* wl = dir ? wl1 : wl0;
    const float* bias = dir ? bias1 : bias0;
    float* cptr = g_gx[dir];

    const int wid = tid >> 5;
    const int lane = tid & 31;
    const int qgid = lane >> 2;
    const int qt4 = lane & 3;
    const int qmw = (wid & 1) * 64;
    const int qnw = (wid >> 1) * 16;
    const int nchunk = kdim >> 6;

    const int lrow = (lane & 7) + ((lane >> 3) & 1) * 8;
    const int lkhalf = (lane >> 4) * 16;
    const int brow = lane & 7;
    const int bkhalf = ((lane >> 3) & 1) * 16;

    float acc[32];
    unsigned fa[16];
    unsigned fg[16];
    unsigned pb[4];
    unsigned qb[4];
#pragma unroll
    for (int i = 0; i < 32; i++) acc[i] = 0.0f;

    copy_tile(qsb, tid, 0, kdim, mbase, nbase, wh, wl);
    copy_tile(qsb + TILE_BYTES, tid, KC, kdim, mbase, nbase, wh, wl);

    for (int c = 0; c < nchunk; c++) {
        if (c + 1 < nchunk) {
            asm volatile("cp.async.wait_group 1;" ::: "memory");
        } else {
            asm volatile("cp.async.wait_group 0;" ::: "memory");
        }
        __syncthreads();
        unsigned qtb = qsb + (unsigned)(c & 1) * TILE_BYTES;
        unsigned abase = qtb + (unsigned)(qmw + lrow) * RSTRIDE + (unsigned)lkhalf;
        unsigned bbase = qtb + (unsigned)(256 + qnw + brow) * RSTRIDE + (unsigned)bkhalf;
#pragma unroll
        for (int kk = 0; kk < KC; kk += 16) {
            unsigned kb = (unsigned)kk * 2u;
#pragma unroll
            for (int mb = 0; mb < 4; mb++) {
                ldmx4(fa + mb * 4, abase + (unsigned)(mb * 16) * RSTRIDE + kb);
                ldmx4(fg + mb * 4, abase + (unsigned)(128 + mb * 16) * RSTRIDE + kb);
            }
#pragma unroll
            for (int nb = 0; nb < 2; nb++) {
                ldmx2(pb + nb * 2, bbase + (unsigned)(nb * 8) * RSTRIDE + kb);
                ldmx2(qb + nb * 2, bbase + (unsigned)(64 + nb * 8) * RSTRIDE + kb);
            }
#pragma unroll
            for (int mb = 0; mb < 4; mb++) {
#pragma unroll
                for (int nb = 0; nb < 2; nb++) {
                    mma_bf16(acc + (mb * 2 + nb) * 4, fa + mb * 4, pb + nb * 2);
                    mma_bf16(acc + (mb * 2 + nb) * 4, fg + mb * 4, pb + nb * 2);
                    mma_bf16(acc + (mb * 2 + nb) * 4, fa + mb * 4, qb + nb * 2);
                }
            }
        }
        __syncthreads();
        if (c + 2 < nchunk) {
            copy_tile(qsb + (unsigned)(c & 1) * TILE_BYTES, tid, (c + 2) * KC,
                      kdim, mbase, nbase, wh, wl);
        }
    }

#pragma unroll
    for (int nb = 0; nb < 2; nb++) {
        int n0 = nbase + qnw + nb * 8 + qt4 * 2;
        float bvx = bias[n0];
        float bvy = bias[n0 + 1];
#pragma unroll
        for (int mb = 0; mb < 4; mb++) {
            int m0 = mbase + qmw + mb * 16 + qgid;
            float* cr = acc + (mb * 2 + nb) * 4;
            float2 u0 = make_float2(cr[0] + bvx, cr[1] + bvy);
            float2 u1 = make_float2(cr[2] + bvx, cr[3] + bvy);
            *(float2*)(cptr + (size_t)m0 * G3 + n0) = u0;
            *(float2*)(cptr + (size_t)(m0 + 8) * G3 + n0) = u1;
        }
    }
}

__global__ __launch_bounds__(512, 1) void gru_layer(
    int layer, const float* __restrict__ bhh_f, const float* __restrict__ bhh_b)
{
    extern __shared__ float smemf[];
    float* wsm  = smemf;
    float2* red = (float2*)(smemf + W_SM_FLOATS);

    const int dir  = blockIdx.y;
    const int jblk = blockIdx.x;
    const int tid  = threadIdx.x;
    const int kg   = tid >> 6;
    const int t64  = tid & 63;
    const int bg   = t64 >> 3;
    const int jp   = t64 & 7;
    const int j0   = jblk * 16 + jp * 2;
    const int b0   = bg * 4;

    const float* wsrc = g_whh_p[layer][dir] + (size_t)jblk * W_SM_FLOATS;
    for (int i = tid; i < W_SM_FLOATS / 4; i += 512)
        ((float4*)wsm)[i] = ((const float4*)wsrc)[i];

    const float* bhh = dir ? bhh_b : bhh_f;
    const float2 br  = *(const float2*)(bhh + j0);
    const float2 bz  = *(const float2*)(bhh + HH + j0);
    const float2 bn2 = *(const float2*)(bhh + 2 * HH + j0);
    const float* gx_base = g_gx[dir];

    float* hst_grp = smemf + W_SM_FLOATS + kg * 1024;
    const unsigned hstg = (unsigned)__cvta_generic_to_shared(hst_grp);
    __syncthreads();

    for (int t = 0; t < SS; t++) {
        const float* hprev = g_h[dir][t & 1];
        const int s_sel = dir ? (SS - 1 - t) : t;
        const float* hsrc = hprev + kg * 128 * BB;

#pragma unroll
        for (int pc = 0; pc < 2; pc++) {
            unsigned dst = hstg + pc * 2048 + t64 * 16;
            const float* src = hsrc + pc * 512 + t64 * 4;
            cpasync16(dst, src);
            cpasync16(dst + 1024, src + 256);
            asm volatile("cp.async.commit_group;" ::: "memory");
        }

        float2 xr[4], xz[4], xn[4];
        float4 hpa, hpb;
        if (kg == 0) {
#pragma unroll
            for (int bi = 0; bi < 4; bi++) {
                const float* gxp = gx_base + ((size_t)s_sel * BB + b0 + bi) * G3 + j0;
                xr[bi] = ldcg2(gxp);
                xz[bi] = ldcg2(gxp + HH);
                xn[bi] = ldcg2(gxp + 2 * HH);
            }
            hpa = ldcg4(hprev + j0 * BB + b0);
            hpb = ldcg4(hprev + (j0 + 1) * BB + b0);
        }

        float2 ar[4], az[4], an[4];
#pragma unroll
        for (int bi = 0; bi < 4; bi++) {
            ar[bi] = make_float2(0.f, 0.f);
            az[bi] = make_float2(0.f, 0.f);
            an[bi] = make_float2(0.f, 0.f);
        }

#pragma unroll
        for (int c = 0; c < 8; c++) {
            if (c < 7) asm volatile("cp.async.wait_group 1;" ::: "memory");
            else       asm volatile("cp.async.wait_group 0;" ::: "memory");
            __syncthreads();
            const float* hst = hst_grp + (c & 1) * 512;
            const float* wq  = wsm + (size_t)(kg * 128 + c * 16) * 48 + jp * 2;
#pragma unroll 4
            for (int kl = 0; kl < 16; kl++) {
                float4 h4 = *(const float4*)&hst[kl * 32 + b0];
                const float* w = wq + kl * 48;
                float2 wr = *(const float2*)(w);
                float2 wz = *(const float2*)(w + 16);
                float2 wn = *(const float2*)(w + 32);
                ar[0] = ffma2(bcast2(h4.x), wr, ar[0]);
                az[0] = ffma2(bcast2(h4.x), wz, az[0]);
                an[0] = ffma2(bcast2(h4.x), wn, an[0]);
                ar[1] = ffma2(bcast2(h4.y), wr, ar[1]);
                az[1] = ffma2(bcast2(h4.y), wz, az[1]);
                an[1] = ffma2(bcast2(h4.y), wn, an[1]);
                ar[2] = ffma2(bcast2(h4.z), wr, ar[2]);
                az[2] = ffma2(bcast2(h4.z), wz, az[2]);
                an[2] = ffma2(bcast2(h4.z), wn, an[2]);
                ar[3] = ffma2(bcast2(h4.w), wr, ar[3]);
                az[3] = ffma2(bcast2(h4.w), wz, az[3]);
                an[3] = ffma2(bcast2(h4.w), wn, an[3]);
            }
            __syncthreads();
            if (c + 2 < 8) {
                unsigned dst = hstg + (c & 1) * 2048 + t64 * 16;
                const float* src = hsrc + (c + 2) * 512 + t64 * 4;
                cpasync16(dst, src);
                cpasync16(dst + 1024, src + 256);
                asm volatile("cp.async.commit_group;" ::: "memory");
            }
        }

        __syncthreads();
        if (kg >= 4) {
            int rbase = (kg - 4) * 768;
#pragma unroll
            for (int bi = 0; bi < 4; bi++) {
                red[rbase + (bi * 3 + 0) * 64 + t64] = ar[bi];
                red[rbase + (bi * 3 + 1) * 64 + t64] = az[bi];
                red[rbase + (bi * 3 + 2) * 64 + t64] = an[bi];
            }
        }
        __syncthreads();
        if (kg < 4) {
            int rbase = kg * 768;
#pragma unroll
            for (int bi = 0; bi < 4; bi++) {
                float2 vr = red[rbase + (bi * 3 + 0) * 64 + t64];
                float2 vz = red[rbase + (bi * 3 + 1) * 64 + t64];
                float2 vn = red[rbase + (bi * 3 + 2) * 64 + t64];
                ar[bi].x += vr.x; ar[bi].y += vr.y;
                az[bi].x += vz.x; az[bi].y += vz.y;
                an[bi].x += vn.x; an[bi].y += vn.y;
            }
        }
        __syncthreads();
        if (kg == 2 || kg == 3) {
            int rbase = (kg - 2) * 768;
#pragma unroll
            for (int bi = 0; bi < 4; bi++) {
                red[rbase + (bi * 3 + 0) * 64 + t64] = ar[bi];
                red[rbase + (bi * 3 + 1) * 64 + t64] = az[bi];
                red[rbase + (bi * 3 + 2) * 64 + t64] = an[bi];
            }
        }
        __syncthreads();
        if (kg < 2) {
            int rbase = kg * 768;
#pragma unroll
            for (int bi = 0; bi < 4; bi++) {
                float2 vr = red[rbase + (bi * 3 + 0) * 64 + t64];
                float2 vz = red[rbase + (bi * 3 + 1) * 64 + t64];
                float2 vn = red[rbase + (bi * 3 + 2) * 64 + t64];
                ar[bi].x += vr.x; ar[bi].y += vr.y;
                az[bi].x += vz.x; az[bi].y += vz.y;
                an[bi].x += vn.x; an[bi].y += vn.y;
            }
        }
        __syncthreads();
        if (kg == 1) {
#pragma unroll
            for (int bi = 0; bi < 4; bi++) {
                red[(bi * 3 + 0) * 64 + t64] = ar[bi];
                red[(bi * 3 + 1) * 64 + t64] = az[bi];
                red[(bi * 3 + 2) * 64 + t64] = an[bi];
            }
        }
        __syncthreads();
        if (kg == 0) {
            float h0n[4], h1n[4];
#pragma unroll
            for (int bi = 0; bi < 4; bi++) {
                float2 vr = red[(bi * 3 + 0) * 64 + t64];
                float2 vz = red[(bi * 3 + 1) * 64 + t64];
                float2 vn = red[(bi * 3 + 2) * 64 + t64];
                float sr0 = xr[bi].x + ar[bi].x + vr.x + br.x;
                float sr1 = xr[bi].y + ar[bi].y + vr.y + br.y;
                float sz0 = xz[bi].x + az[bi].x + vz.x + bz.x;
                float sz1 = xz[bi].y + az[bi].y + vz.y + bz.y;
                float sn0 = an[bi].x + vn.x + bn2.x;
                float sn1 = an[bi].y + vn.y + bn2.y;
                float r0 = sigmoidf_(sr0), r1 = sigmoidf_(sr1);
                float z0 = sigmoidf_(sz0), z1 = sigmoidf_(sz1);
                float n0 = tanh_fast(xn[bi].x + r0 * sn0);
                float n1 = tanh_fast(xn[bi].y + r1 * sn1);
                float hp0 = (bi == 0) ? hpa.x : (bi == 1) ? hpa.y : (bi == 2) ? hpa.z : hpa.w;
                float hp1 = (bi == 0) ? hpb.x : (bi == 1) ? hpb.y : (bi == 2) ? hpb.z : hpb.w;
                h0n[bi] = (1.f - z0) * n0 + z0 * hp0;
                h1n[bi] = (1.f - z1) * n1 + z1 * hp1;
            }
            float* hout = g_h[dir][(t + 1) & 1];
            *(float4*)(hout + j0 * BB + b0) = make_float4(h0n[0], h0n[1], h0n[2], h0n[3]);
            *(float4*)(hout + (j0 + 1) * BB + b0) = make_float4(h1n[0], h1n[1], h1n[2], h1n[3]);
            if (layer == 0) {
#pragma unroll
                for (int bi = 0; bi < 4; bi++) {
                    size_t aoff = ((size_t)s_sel * BB + b0 + bi) * H2 + dir * HH + j0;
                    __nv_bfloat16 p0 = __float2bfloat16_rn(h0n[bi]);
                    __nv_bfloat16 p1 = __float2bfloat16_rn(h1n[bi]);
                    g_ahi[aoff]     = p0;
                    g_ahi[aoff + 1] = p1;
                    g_alo[aoff]     = __float2bfloat16_rn(h0n[bi] - __bfloat162float(p0));
                    g_alo[aoff + 1] = __float2bfloat16_rn(h1n[bi] - __bfloat162float(p1));
                }
            }
        }

        dir_barrier(dir, (unsigned)(t + 1));
    }
}

__global__ void zero_h_k() {
    int i = blockIdx.x * blockDim.x + threadIdx.x;
    if (i < HH * BB) { g_h[0][0][i] = 0.f; g_h[1][0][i] = 0.f; }
    if (i < 2) g_bar_count[i] = 0u;
}

__global__ void finalize_k(float* __restrict__ out) {
    int i = blockIdx.x * blockDim.x + threadIdx.x;
    if (i < BB * H2) {
        int b = i >> 11, c = i & 2047;
        out[i] = (c < HH) ? g_h[0][0][c * BB + b] : g_h[1][0][(c - HH) * BB + b];
    }
}

extern "C" void kernel_launch(void* const* d_in, const int* in_sizes, int n_in,
                              void* d_out, int out_size)
{
    const float* x       = (const float*)d_in[0];
    const float* w_ih_f0 = (const float*)d_in[1];
    const float* w_hh_f0 = (const float*)d_in[2];
    const float* b_ih_f0 = (const float*)d_in[3];
    const float* b_hh_f0 = (const float*)d_in[4];
    const float* w_ih_b0 = (const float*)d_in[5];
    const float* w_hh_b0 = (const float*)d_in[6];
    const float* b_ih_b0 = (const float*)d_in[7];
    const float* b_hh_b0 = (const float*)d_in[8];
    const float* w_ih_f1 = (const float*)d_in[9];
    const float* w_hh_f1 = (const float*)d_in[10];
    const float* b_ih_f1 = (const float*)d_in[11];
    const float* b_hh_f1 = (const float*)d_in[12];
    const float* w_ih_b1 = (const float*)d_in[13];
    const float* w_hh_b1 = (const float*)d_in[14];
    const float* b_ih_b1 = (const float*)d_in[15];
    const float* b_hh_b1 = (const float*)d_in[16];
    float* out = (float*)d_out;

    cudaFuncSetAttribute(gru_layer, cudaFuncAttributeMaxDynamicSharedMemorySize,
                         GRU_SMEM_BYTES);
    cudaFuncSetAttribute(gemm_hmma, cudaFuncAttributeMaxDynamicSharedMemorySize,
                         GEMM_SMEM_BYTES);

    void *whi_v, *wlo_v;
    cudaGetSymbolAddress(&whi_v, g_whi);
    cudaGetSymbolAddress(&wlo_v, g_wlo);
    __nv_bfloat16* whi = (__nv_bfloat16*)whi_v;
    __nv_bfloat16* wlo = (__nv_bfloat16*)wlo_v;

    dim3 ggrid(G3 / 64, MTOT / 128, 2);

    conv_x<<<(MTOT * II) / 256, 256>>>(x);
    conv_w<<<dim3(24576, 4), 256>>>(w_ih_f0, w_ih_b0, w_ih_f1, w_ih_b1);
    prepack_whh<<<dim3(12288, 4), 256>>>(w_hh_f0, w_hh_b0, w_hh_f1, w_hh_b1);
    gemm_hmma<<<ggrid, 256, GEMM_SMEM_BYTES>>>(
        whi + WOFF_F0, wlo + WOFF_F0, whi + WOFF_B0, wlo + WOFF_B0,
        b_ih_f0, b_ih_b0, 512);
    gru_layer<<<dim3(64, 2), 512, GRU_SMEM_BYTES>>>(0, b_hh_f0, b_hh_b0);
    gemm_hmma<<<ggrid, 256, GEMM_SMEM_BYTES>>>(
        whi + WOFF_F1, wlo + WOFF_F1, whi + WOFF_B1, wlo + WOFF_B1,
        b_ih_f1, b_ih_b1, 2048);
    zero_h_k<<<(HH * BB + 255) / 256, 256>>>();
    gru_layer<<<dim3(64, 2), 512, GRU_SMEM_BYTES>>>(1, b_hh_f1, b_hh_b1);

    finalize_k<<<(BB * H2 + 255) / 256, 256>>>(out);
}

// round 17
// speedup vs baseline: 1.5490x; 1.0001x over previous
#include <cuda_runtime.h>
#include <cuda_bf16.h>
#include <math.h>

#define BB 32
#define SS 512
#define II 512
#define HH 1024
#define G3 3072
#define H2 2048
#define MTOT (BB * SS)

#define W_SM_FLOATS (1024 * 48)
#define HSTAGE_FLOATS (8 * 2 * 512)
#define GRU_SMEM_BYTES ((W_SM_FLOATS + HSTAGE_FLOATS) * 4)

#define KC 64
#define RSTRIDE 144
#define TILE_BYTES (384 * RSTRIDE)
#define GEMM_SMEM_BYTES (2 * TILE_BYTES)

#define WOFF_F0 0
#define WOFF_B0 (3072 * 512)
#define WOFF_F1 (2 * 3072 * 512)
#define WOFF_B1 (2 * 3072 * 512 + 3072 * 2048)
#define WTOT (2 * 3072 * 512 + 2 * 3072 * 2048)

__device__ float g_whh_p[2][2][HH * G3];
__device__ float g_gx[2][(size_t)MTOT * G3];
__device__ float g_h[2][2][HH * BB];
__device__ unsigned g_bar_count[2];
__device__ __align__(256) __nv_bfloat16 g_ahi[(size_t)MTOT * H2];
__device__ __align__(256) __nv_bfloat16 g_alo[(size_t)MTOT * H2];
__device__ __align__(256) __nv_bfloat16 g_whi[WTOT];
__device__ __align__(256) __nv_bfloat16 g_wlo[WTOT];

__device__ __forceinline__ float2 ffma2(float2 a, float2 b, float2 c) {
    unsigned long long A = *reinterpret_cast<unsigned long long*>(&a);
    unsigned long long B = *reinterpret_cast<unsigned long long*>(&b);
    unsigned long long C = *reinterpret_cast<unsigned long long*>(&c);
    unsigned long long D;
    asm("fma.rn.f32x2 %0, %1, %2, %3;" : "=l"(D) : "l"(A), "l"(B), "l"(C));
    return *reinterpret_cast<float2*>(&D);
}
__device__ __forceinline__ float2 bcast2(float x) { return make_float2(x, x); }
__device__ __forceinline__ float tanh_fast(float x) {
    float y;
    asm("tanh.approx.f32 %0, %1;" : "=f"(y) : "f"(x));
    return y;
}
__device__ __forceinline__ float sigmoidf_(float x) {
    return fmaf(0.5f, tanh_fast(0.5f * x), 0.5f);
}
__device__ __forceinline__ float4 ldcg4(const float* p) {
    float4 v;
    asm volatile("ld.global.cg.v4.f32 {%0,%1,%2,%3}, [%4];"
                 : "=f"(v.x), "=f"(v.y), "=f"(v.z), "=f"(v.w) : "l"(p));
    return v;
}
__device__ __forceinline__ float2 ldcg2(const float* p) {
    float2 v;
    asm volatile("ld.global.cg.v2.f32 {%0,%1}, [%2];" : "=f"(v.x), "=f"(v.y) : "l"(p));
    return v;
}
__device__ __forceinline__ void cpasync16(unsigned dst, const void* src) {
    asm volatile("cp.async.cg.shared.global [%0], [%1], 16;" :: "r"(dst), "l"(src) : "memory");
}
__device__ __forceinline__ void ldmx4(unsigned* r, unsigned addr) {
    asm volatile("ldmatrix.sync.aligned.m8n8.x4.shared.b16 {%0,%1,%2,%3}, [%4];"
                 : "=r"(r[0]), "=r"(r[1]), "=r"(r[2]), "=r"(r[3]) : "r"(addr));
}
__device__ __forceinline__ void ldmx2(unsigned* r, unsigned addr) {
    asm volatile("ldmatrix.sync.aligned.m8n8.x2.shared.b16 {%0,%1}, [%2];"
                 : "=r"(r[0]), "=r"(r[1]) : "r"(addr));
}
__device__ __forceinline__ void mma_bf16(float* c, const unsigned* a, const unsigned* b) {
    asm volatile(
        "mma.sync.aligned.m16n8k16.row.col.f32.bf16.bf16.f32 "
        "{%0,%1,%2,%3}, {%4,%5,%6,%7}, {%8,%9}, {%0,%1,%2,%3};"
        : "+f"(c[0]), "+f"(c[1]), "+f"(c[2]), "+f"(c[3])
        : "r"(a[0]), "r"(a[1]), "r"(a[2]), "r"(a[3]), "r"(b[0]), "r"(b[1]));
}

__device__ __forceinline__ void dir_barrier(int dir, unsigned n) {
    __syncthreads();
    if (threadIdx.x == 0) {
        unsigned* cnt = &g_bar_count[dir];
        asm volatile("red.release.gpu.global.add.u32 [%0], 1;" :: "l"(cnt) : "memory");
        const unsigned target = n * 64u;
        unsigned cur;
        do {
            asm volatile("ld.acquire.gpu.global.u32 %0, [%1];"
                         : "=r"(cur) : "l"(cnt) : "memory");
            if (cur >= target) break;
            __nanosleep(16);
        } while (true);
    }
    __syncthreads();
}

__global__ void conv_x(const float* __restrict__ x) {
    size_t idx = (size_t)blockIdx.x * 256 + threadIdx.x;
    int m = (int)(idx >> 9);
    int k = (int)(idx & 511);
    int b = m & 31;
    int s = m >> 5;
    float v = x[((size_t)b * SS + s) * II + k];
    __nv_bfloat16 hi = __float2bfloat16_rn(v);
    g_ahi[idx] = hi;
    g_alo[idx] = __float2bfloat16_rn(v - __bfloat162float(hi));
}

__global__ void conv_w(const float* w_f0, const float* w_b0,
                       const float* w_f1, const float* w_b1) {
    int mat = blockIdx.y;
    size_t sz  = (mat < 2) ? (size_t)3072 * 512 : (size_t)3072 * 2048;
    size_t off = (mat == 0) ? WOFF_F0 : (mat == 1) ? WOFF_B0 : (mat == 2) ? WOFF_F1 : WOFF_B1;
    const float* src = (mat == 0) ? w_f0 : (mat == 1) ? w_b0 : (mat == 2) ? w_f1 : w_b1;
    size_t idx = (size_t)blockIdx.x * 256 + threadIdx.x;
    if (idx >= sz) return;
    float v = src[idx];
    __nv_bfloat16 hi = __float2bfloat16_rn(v);
    g_whi[off + idx] = hi;
    g_wlo[off + idx] = __float2bfloat16_rn(v - __bfloat162float(hi));
}

__global__ void prepack_whh(const float* w00, const float* w01,
                            const float* w10, const float* w11) {
    int mat = blockIdx.y;
    const float* src = (mat == 0) ? w00 : (mat == 1) ? w01 : (mat == 2) ? w10 : w11;
    float* dst = g_whh_p[mat >> 1][mat & 1];
    int idx = blockIdx.x * 256 + threadIdx.x;
    int k = idx & 1023;
    int n = idx >> 10;
    int g = n >> 10;
    int nj = n & 1023;
    int jblk = nj >> 4;
    int jp = (nj >> 1) & 7;
    int c  = nj & 1;
    dst[jblk * W_SM_FLOATS + k * 48 + g * 16 + jp * 2 + c] = src[idx];
    if (mat == 0) {
        if (idx < HH * BB) { g_h[0][0][idx] = 0.f; g_h[1][0][idx] = 0.f; }
        if (idx < 2) g_bar_count[idx] = 0u;
    }
}

__device__ __forceinline__ void copy_tile(
    unsigned dstbase, int tid, int kpos, int kdim, int mbase, int nbase,
    const __nv_bfloat16* wh, const __nv_bfloat16* wl)
{
#pragma unroll
    for (int j = 0; j < 12; j++) {
        int seg = tid + 256 * j;
        int rr = seg >> 3;
        int oo = seg & 7;
        unsigned d = dstbase + (unsigned)rr * RSTRIDE + (unsigned)oo * 16;
        const __nv_bfloat16* s;
        if (rr < 128) {
            s = g_ahi + (size_t)(mbase + rr) * kdim + kpos + oo * 8;
        } else if (rr < 256) {
            s = g_alo + (size_t)(mbase + rr - 128) * kdim + kpos + oo * 8;
        } else if (rr < 320) {
            s = wh + (size_t)(nbase + rr - 256) * kdim + kpos + oo * 8;
        } else {
            s = wl + (size_t)(nbase + rr - 320) * kdim + kpos + oo * 8;
        }
        cpasync16(d, s);
    }
    asm volatile("cp.async.commit_group;" ::: "memory");
}

__global__ __launch_bounds__(256, 2) void gemm_hmma(
    const __nv_bfloat16* __restrict__ wh0, const __nv_bfloat16* __restrict__ wl0,
    const __nv_bfloat16* __restrict__ wh1, const __nv_bfloat16* __restrict__ wl1,
    const float* __restrict__ bias0, const float* __restrict__ bias1, int kdim)
{
    extern __shared__ char smem[];
    const unsigned qsb = (unsigned)__cvta_generic_to_shared(smem);
    const int tid = threadIdx.x;
    const int nbase = blockIdx.x * 64;
    const int mbase = blockIdx.y * 128;
    const int dir = blockIdx.z;
    const __nv_bfloat16* wh = dir ? wh1 : wh0;
    const __nv_bfloat16* wl = dir ? wl1 : wl0;
    const float* bias = dir ? bias1 : bias0;
    float* cptr = g_gx[dir];

    const int wid = tid >> 5;
    const int lane = tid & 31;
    const int qgid = lane >> 2;
    const int qt4 = lane & 3;
    const int qmw = (wid & 1) * 64;
    const int qnw = (wid >> 1) * 16;
    const int nchunk = kdim >> 6;

    const int lrow = (lane & 7) + ((lane >> 3) & 1) * 8;
    const int lkhalf = (lane >> 4) * 16;
    const int brow = lane & 7;
    const int bkhalf = ((lane >> 3) & 1) * 16;

    float acc[32];
    unsigned fa[16];
    unsigned fg[16];
    unsigned pb[4];
    unsigned qb[4];
#pragma unroll
    for (int i = 0; i < 32; i++) acc[i] = 0.0f;

    copy_tile(qsb, tid, 0, kdim, mbase, nbase, wh, wl);
    copy_tile(qsb + TILE_BYTES, tid, KC, kdim, mbase, nbase, wh, wl);

    for (int c = 0; c < nchunk; c++) {
        if (c + 1 < nchunk) {
            asm volatile("cp.async.wait_group 1;" ::: "memory");
        } else {
            asm volatile("cp.async.wait_group 0;" ::: "memory");
        }
        __syncthreads();
        unsigned qtb = qsb + (unsigned)(c & 1) * TILE_BYTES;
        unsigned abase = qtb + (unsigned)(qmw + lrow) * RSTRIDE + (unsigned)lkhalf;
        unsigned bbase = qtb + (unsigned)(256 + qnw + brow) * RSTRIDE + (unsigned)bkhalf;
#pragma unroll
        for (int kk = 0; kk < KC; kk += 16) {
            unsigned kb = (unsigned)kk * 2u;
#pragma unroll
            for (int mb = 0; mb < 4; mb++) {
                ldmx4(fa + mb * 4, abase + (unsigned)(mb * 16) * RSTRIDE + kb);
                ldmx4(fg + mb * 4, abase + (unsigned)(128 + mb * 16) * RSTRIDE + kb);
            }
#pragma unroll
            for (int nb = 0; nb < 2; nb++) {
                ldmx2(pb + nb * 2, bbase + (unsigned)(nb * 8) * RSTRIDE + kb);
                ldmx2(qb + nb * 2, bbase + (unsigned)(64 + nb * 8) * RSTRIDE + kb);
            }
#pragma unroll
            for (int mb = 0; mb < 4; mb++) {
#pragma unroll
                for (int nb = 0; nb < 2; nb++) {
                    mma_bf16(acc + (mb * 2 + nb) * 4, fa + mb * 4, pb + nb * 2);
                }
            }
#pragma unroll
            for (int mb = 0; mb < 4; mb++) {
#pragma unroll
                for (int nb = 0; nb < 2; nb++) {
                    mma_bf16(acc + (mb * 2 + nb) * 4, fg + mb * 4, pb + nb * 2);
                }
            }
#pragma unroll
            for (int mb = 0; mb < 4; mb++) {
#pragma unroll
                for (int nb = 0; nb < 2; nb++) {
                    mma_bf16(acc + (mb * 2 + nb) * 4, fa + mb * 4, qb + nb * 2);
                }
            }
        }
        __syncthreads();
        if (c + 2 < nchunk) {
            copy_tile(qsb + (unsigned)(c & 1) * TILE_BYTES, tid, (c + 2) * KC,
                      kdim, mbase, nbase, wh, wl);
        }
    }

#pragma unroll
    for (int nb = 0; nb < 2; nb++) {
        int n0 = nbase + qnw + nb * 8 + qt4 * 2;
        float bvx = bias[n0];
        float bvy = bias[n0 + 1];
#pragma unroll
        for (int mb = 0; mb < 4; mb++) {
            int m0 = mbase + qmw + mb * 16 + qgid;
            float* cr = acc + (mb * 2 + nb) * 4;
            float2 u0 = make_float2(cr[0] + bvx, cr[1] + bvy);
            float2 u1 = make_float2(cr[2] + bvx, cr[3] + bvy);
            *(float2*)(cptr + (size_t)m0 * G3 + n0) = u0;
            *(float2*)(cptr + (size_t)(m0 + 8) * G3 + n0) = u1;
        }
    }
}

__global__ __launch_bounds__(512, 1) void gru_layer(
    int layer, const float* __restrict__ bhh_f, const float* __restrict__ bhh_b)
{
    extern __shared__ float smemf[];
    float* wsm  = smemf;
    float2* red = (float2*)(smemf + W_SM_FLOATS);

    const int dir  = blockIdx.y;
    const int jblk = blockIdx.x;
    const int tid  = threadIdx.x;
    const int kg   = tid >> 6;
    const int t64  = tid & 63;
    const int bg   = t64 >> 3;
    const int jp   = t64 & 7;
    const int j0   = jblk * 16 + jp * 2;
    const int b0   = bg * 4;

    const float* wsrc = g_whh_p[layer][dir] + (size_t)jblk * W_SM_FLOATS;
    for (int i = tid; i < W_SM_FLOATS / 4; i += 512)
        ((float4*)wsm)[i] = ((const float4*)wsrc)[i];

    const float* bhh = dir ? bhh_b : bhh_f;
    const float2 br  = *(const float2*)(bhh + j0);
    const float2 bz  = *(const float2*)(bhh + HH + j0);
    const float2 bn2 = *(const float2*)(bhh + 2 * HH + j0);
    const float* gx_base = g_gx[dir];

    float* hst_grp = smemf + W_SM_FLOATS + kg * 1024;
    const unsigned hstg = (unsigned)__cvta_generic_to_shared(hst_grp);
    __syncthreads();

    for (int t = 0; t < SS; t++) {
        const float* hprev = g_h[dir][t & 1];
        const int s_sel = dir ? (SS - 1 - t) : t;
        const float* hsrc = hprev + kg * 128 * BB;

#pragma unroll
        for (int pc = 0; pc < 2; pc++) {
            unsigned dst = hstg + pc * 2048 + t64 * 16;
            const float* src = hsrc + pc * 512 + t64 * 4;
            cpasync16(dst, src);
            cpasync16(dst + 1024, src + 256);
            asm volatile("cp.async.commit_group;" ::: "memory");
        }

        float2 xr[4], xz[4], xn[4];
        float4 hpa, hpb;
        if (kg == 0) {
#pragma unroll
            for (int bi = 0; bi < 4; bi++) {
                const float* gxp = gx_base + ((size_t)s_sel * BB + b0 + bi) * G3 + j0;
                xr[bi] = ldcg2(gxp);
                xz[bi] = ldcg2(gxp + HH);
                xn[bi] = ldcg2(gxp + 2 * HH);
            }
            hpa = ldcg4(hprev + j0 * BB + b0);
            hpb = ldcg4(hprev + (j0 + 1) * BB + b0);
        }

        float2 ar[4], az[4], an[4];
#pragma unroll
        for (int bi = 0; bi < 4; bi++) {
            ar[bi] = make_float2(0.f, 0.f);
            az[bi] = make_float2(0.f, 0.f);
            an[bi] = make_float2(0.f, 0.f);
        }

#pragma unroll
        for (int c = 0; c < 8; c++) {
            if (c < 7) asm volatile("cp.async.wait_group 1;" ::: "memory");
            else       asm volatile("cp.async.wait_group 0;" ::: "memory");
            __syncthreads();
            const float* hst = hst_grp + (c & 1) * 512;
            const float* wq  = wsm + (size_t)(kg * 128 + c * 16) * 48 + jp * 2;
#pragma unroll 4
            for (int kl = 0; kl < 16; kl++) {
                float4 h4 = *(const float4*)&hst[kl * 32 + b0];
                const float* w = wq + kl * 48;
                float2 wr = *(const float2*)(w);
                float2 wz = *(const float2*)(w + 16);
                float2 wn = *(const float2*)(w + 32);
                ar[0] = ffma2(bcast2(h4.x), wr, ar[0]);
                az[0] = ffma2(bcast2(h4.x), wz, az[0]);
                an[0] = ffma2(bcast2(h4.x), wn, an[0]);
                ar[1] = ffma2(bcast2(h4.y), wr, ar[1]);
                az[1] = ffma2(bcast2(h4.y), wz, az[1]);
                an[1] = ffma2(bcast2(h4.y), wn, an[1]);
                ar[2] = ffma2(bcast2(h4.z), wr, ar[2]);
                az[2] = ffma2(bcast2(h4.z), wz, az[2]);
                an[2] = ffma2(bcast2(h4.z), wn, an[2]);
                ar[3] = ffma2(bcast2(h4.w), wr, ar[3]);
                az[3] = ffma2(bcast2(h4.w), wz, az[3]);
                an[3] = ffma2(bcast2(h4.w), wn, an[3]);
            }
            __syncthreads();
            if (c + 2 < 8) {
                unsigned dst = hstg + (c & 1) * 2048 + t64 * 16;
                const float* src = hsrc + (c + 2) * 512 + t64 * 4;
                cpasync16(dst, src);
                cpasync16(dst + 1024, src + 256);
                asm volatile("cp.async.commit_group;" ::: "memory");
            }
        }

        __syncthreads();
        if (kg >= 4) {
            int rbase = (kg - 4) * 768;
#pragma unroll
            for (int bi = 0; bi < 4; bi++) {
                red[rbase + (bi * 3 + 0) * 64 + t64] = ar[bi];
                red[rbase + (bi * 3 + 1) * 64 + t64] = az[bi];
                red[rbase + (bi * 3 + 2) * 64 + t64] = an[bi];
            }
        }
        __syncthreads();
        if (kg < 4) {
            int rbase = kg * 768;
#pragma unroll
            for (int bi = 0; bi < 4; bi++) {
                float2 vr = red[rbase + (bi * 3 + 0) * 64 + t64];
                float2 vz = red[rbase + (bi * 3 + 1) * 64 + t64];
                float2 vn = red[rbase + (bi * 3 + 2) * 64 + t64];
                ar[bi].x += vr.x; ar[bi].y += vr.y;
                az[bi].x += vz.x; az[bi].y += vz.y;
                an[bi].x += vn.x; an[bi].y += vn.y;
            }
        }
        __syncthreads();
        if (kg == 2 || kg == 3) {
            int rbase = (kg - 2) * 768;
#pragma unroll
            for (int bi = 0; bi < 4; bi++) {
                red[rbase + (bi * 3 + 0) * 64 + t64] = ar[bi];
                red[rbase + (bi * 3 + 1) * 64 + t64] = az[bi];
                red[rbase + (bi * 3 + 2) * 64 + t64] = an[bi];
            }
        }
        __syncthreads();
        if (kg < 2) {
            int rbase = kg * 768;
#pragma unroll
            for (int bi = 0; bi < 4; bi++) {
                float2 vr = red[rbase + (bi * 3 + 0) * 64 + t64];
                float2 vz = red[rbase + (bi * 3 + 1) * 64 + t64];
                float2 vn = red[rbase + (bi * 3 + 2) * 64 + t64];
                ar[bi].x += vr.x; ar[bi].y += vr.y;
                az[bi].x += vz.x; az[bi].y += vz.y;
                an[bi].x += vn.x; an[bi].y += vn.y;
            }
        }
        __syncthreads();
        if (kg == 1) {
#pragma unroll
            for (int bi = 0; bi < 4; bi++) {
                red[(bi * 3 + 0) * 64 + t64] = ar[bi];
                red[(bi * 3 + 1) * 64 + t64] = az[bi];
                red[(bi * 3 + 2) * 64 + t64] = an[bi];
            }
        }
        __syncthreads();
        if (kg == 0) {
            float h0n[4], h1n[4];
#pragma unroll
            for (int bi = 0; bi < 4; bi++) {
                float2 vr = red[(bi * 3 + 0) * 64 + t64];
                float2 vz = red[(bi * 3 + 1) * 64 + t64];
                float2 vn = red[(bi * 3 + 2) * 64 + t64];
                float sr0 = xr[bi].x + ar[bi].x + vr.x + br.x;
                float sr1 = xr[bi].y + ar[bi].y + vr.y + br.y;
                float sz0 = xz[bi].x + az[bi].x + vz.x + bz.x;
                float sz1 = xz[bi].y + az[bi].y + vz.y + bz.y;
                float sn0 = an[bi].x + vn.x + bn2.x;
                float sn1 = an[bi].y + vn.y + bn2.y;
                float r0 = sigmoidf_(sr0), r1 = sigmoidf_(sr1);
                float z0 = sigmoidf_(sz0), z1 = sigmoidf_(sz1);
                float n0 = tanh_fast(xn[bi].x + r0 * sn0);
                float n1 = tanh_fast(xn[bi].y + r1 * sn1);
                float hp0 = (bi == 0) ? hpa.x : (bi == 1) ? hpa.y : (bi == 2) ? hpa.z : hpa.w;
                float hp1 = (bi == 0) ? hpb.x : (bi == 1) ? hpb.y : (bi == 2) ? hpb.z : hpb.w;
                h0n[bi] = (1.f - z0) * n0 + z0 * hp0;
                h1n[bi] = (1.f - z1) * n1 + z1 * hp1;
            }
            float* hout = g_h[dir][(t + 1) & 1];
            *(float4*)(hout + j0 * BB + b0) = make_float4(h0n[0], h0n[1], h0n[2], h0n[3]);
            *(float4*)(hout + (j0 + 1) * BB + b0) = make_float4(h1n[0], h1n[1], h1n[2], h1n[3]);
            if (layer == 0) {
#pragma unroll
                for (int bi = 0; bi < 4; bi++) {
                    size_t aoff = ((size_t)s_sel * BB + b0 + bi) * H2 + dir * HH + j0;
                    __nv_bfloat16 p0 = __float2bfloat16_rn(h0n[bi]);
                    __nv_bfloat16 p1 = __float2bfloat16_rn(h1n[bi]);
                    g_ahi[aoff]     = p0;
                    g_ahi[aoff + 1] = p1;
                    g_alo[aoff]     = __float2bfloat16_rn(h0n[bi] - __bfloat162float(p0));
                    g_alo[aoff + 1] = __float2bfloat16_rn(h1n[bi] - __bfloat162float(p1));
                }
            }
        }

        dir_barrier(dir, (unsigned)(t + 1));
    }
}

__global__ void zero_h_k() {
    int i = blockIdx.x * blockDim.x + threadIdx.x;
    if (i < HH * BB) { g_h[0][0][i] = 0.f; g_h[1][0][i] = 0.f; }
    if (i < 2) g_bar_count[i] = 0u;
}

__global__ void finalize_k(float* __restrict__ out) {
    int i = blockIdx.x * blockDim.x + threadIdx.x;
    if (i < BB * H2) {
        int b = i >> 11, c = i & 2047;
        out[i] = (c < HH) ? g_h[0][0][c * BB + b] : g_h[1][0][(c - HH) * BB + b];
    }
}

extern "C" void kernel_launch(void* const* d_in, const int* in_sizes, int n_in,
                              void* d_out, int out_size)
{
    const float* x       = (const float*)d_in[0];
    const float* w_ih_f0 = (const float*)d_in[1];
    const float* w_hh_f0 = (const float*)d_in[2];
    const float* b_ih_f0 = (const float*)d_in[3];
    const float* b_hh_f0 = (const float*)d_in[4];
    const float* w_ih_b0 = (const float*)d_in[5];
    const float* w_hh_b0 = (const float*)d_in[6];
    const float* b_ih_b0 = (const float*)d_in[7];
    const float* b_hh_b0 = (const float*)d_in[8];
    const float* w_ih_f1 = (const float*)d_in[9];
    const float* w_hh_f1 = (const float*)d_in[10];
    const float* b_ih_f1 = (const float*)d_in[11];
    const float* b_hh_f1 = (const float*)d_in[12];
    const float* w_ih_b1 = (const float*)d_in[13];
    const float* w_hh_b1 = (const float*)d_in[14];
    const float* b_ih_b1 = (const float*)d_in[15];
    const float* b_hh_b1 = (const float*)d_in[16];
    float* out = (float*)d_out;

    cudaFuncSetAttribute(gru_layer, cudaFuncAttributeMaxDynamicSharedMemorySize,
                         GRU_SMEM_BYTES);
    cudaFuncSetAttribute(gemm_hmma, cudaFuncAttributeMaxDynamicSharedMemorySize,
                         GEMM_SMEM_BYTES);

    void *whi_v, *wlo_v;
    cudaGetSymbolAddress(&whi_v, g_whi);
    cudaGetSymbolAddress(&wlo_v, g_wlo);
    __nv_bfloat16* whi = (__nv_bfloat16*)whi_v;
    __nv_bfloat16* wlo = (__nv_bfloat16*)wlo_v;

    dim3 ggrid(G3 / 64, MTOT / 128, 2);

    conv_x<<<(MTOT * II) / 256, 256>>>(x);
    conv_w<<<dim3(24576, 4), 256>>>(w_ih_f0, w_ih_b0, w_ih_f1, w_ih_b1);
    prepack_whh<<<dim3(12288, 4), 256>>>(w_hh_f0, w_hh_b0, w_hh_f1, w_hh_b1);
    gemm_hmma<<<ggrid, 256, GEMM_SMEM_BYTES>>>(
        whi + WOFF_F0, wlo + WOFF_F0, whi + WOFF_B0, wlo + WOFF_B0,
        b_ih_f0, b_ih_b0, 512);
    gru_layer<<<dim3(64, 2), 512, GRU_SMEM_BYTES>>>(0, b_hh_f0, b_hh_b0);
    gemm_hmma<<<ggrid, 256, GEMM_SMEM_BYTES>>>(
        whi + WOFF_F1, wlo + WOFF_F1, whi + WOFF_B1, wlo + WOFF_B1,
        b_ih_f1, b_ih_b1, 2048);
    zero_h_k<<<(HH * BB + 255) / 256, 256>>>();
    gru_layer<<<dim3(64, 2), 512, GRU_SMEM_BYTES>>>(1, b_hh_f1, b_hh_b1);

    finalize_k<<<(BB * H2 + 255) / 256, 256>>>(out);
}